// round 1
// baseline (speedup 1.0000x reference)
#include <cuda_runtime.h>

#define KL 4096
#define KB 4
#define KD 512
#define KV 1000

// ---- scratch (static device globals; no allocations) ----
__device__ float g_part[KB * 16 * KD];        // partial column sums
__device__ float g_s[KB * KD];                // s[b][d] = sum_l X[l][d]
__device__ float g_G[KB * KD * KD];           // G[b] = X^T X          (4 MB)
__device__ float g_M[KB * KD * KD];           // M[b] = Ww G + Wb s^T  (4 MB)
__device__ float g_y[(size_t)KB * KL * KD];   // y[b] = X M            (33.5 MB)
__device__ float g_logits[(size_t)KB * KL * KV]; // logits rows (b*L+l) (65.5 MB)

// ---------------------------------------------------------------------------
// Column sums: s[b][d] = sum_l x[l][b][d]   (two-stage, no atomics)
// ---------------------------------------------------------------------------
__global__ void colsum_part_k(const float* __restrict__ x) {
    int b = blockIdx.y, slab = blockIdx.x;   // 16 slabs of L/16 rows
    int d = threadIdx.x;                     // 256 threads -> d and d+256
    const float* base = x + b * KD;
    float s0 = 0.f, s1 = 0.f;
    int l0 = slab * (KL / 16);
#pragma unroll 4
    for (int l = l0; l < l0 + (KL / 16); ++l) {
        s0 += base[(size_t)l * (KB * KD) + d];
        s1 += base[(size_t)l * (KB * KD) + d + 256];
    }
    g_part[(b * 16 + slab) * KD + d] = s0;
    g_part[(b * 16 + slab) * KD + d + 256] = s1;
}

__global__ void colsum_final_k() {
    int idx = blockIdx.x * 256 + threadIdx.x;  // KB*KD = 2048 threads
    int b = idx / KD, d = idx % KD;
    float s = 0.f;
#pragma unroll
    for (int k = 0; k < 16; k++) s += g_part[(b * 16 + k) * KD + d];
    g_s[idx] = s;
}

// ---------------------------------------------------------------------------
// G[b] = X^T X : 64x64 tile, K=L=4096, both operands K-major strided views of x
// ---------------------------------------------------------------------------
__global__ __launch_bounds__(256) void gemm_G_k(const float* __restrict__ x) {
    int b = blockIdx.z;
    int i0 = blockIdx.x * 64, j0 = blockIdx.y * 64;
    __shared__ float As[16][64];
    __shared__ float Bs[16][64];
    const float* A = x + b * KD;  // element (k,i): A[k*(KB*KD) + i]
    int tid = threadIdx.x;
    int lr = tid >> 4, lc = (tid & 15) << 2;
    int ty = tid >> 4, tx = tid & 15;
    float acc[4][4] = {};
    for (int kb = 0; kb < KL; kb += 16) {
        const float* rowp = A + (size_t)(kb + lr) * (KB * KD);
        *(float4*)&As[lr][lc] = *(const float4*)(rowp + i0 + lc);
        *(float4*)&Bs[lr][lc] = *(const float4*)(rowp + j0 + lc);
        __syncthreads();
#pragma unroll
        for (int k = 0; k < 16; k++) {
            float a[4], bb[4];
            *(float4*)a = *(const float4*)&As[k][ty * 4];
            *(float4*)bb = *(const float4*)&Bs[k][tx * 4];
#pragma unroll
            for (int ii = 0; ii < 4; ii++)
#pragma unroll
                for (int jj = 0; jj < 4; jj++) acc[ii][jj] += a[ii] * bb[jj];
        }
        __syncthreads();
    }
    float* C = g_G + (size_t)b * KD * KD;
#pragma unroll
    for (int ii = 0; ii < 4; ii++)
        *(float4*)&C[(size_t)(i0 + ty * 4 + ii) * KD + j0 + tx * 4] = *(float4*)acc[ii];
}

// ---------------------------------------------------------------------------
// M[b] = Ww * G[b] + Wb (outer) s[b] : 64x64 tile, K=512
//   A = Ww (row-major M x K -> loaded transposed), B = G[b] (K-major)
// ---------------------------------------------------------------------------
__global__ __launch_bounds__(256) void gemm_M_k(const float* __restrict__ Ww,
                                                const float* __restrict__ Wb) {
    int b = blockIdx.z;
    int i0 = blockIdx.x * 64, j0 = blockIdx.y * 64;
    __shared__ float As[16][64];
    __shared__ float Bs[16][64];
    const float* Bmat = g_G + (size_t)b * KD * KD;
    int tid = threadIdx.x;
    int ai = tid >> 2, akq = (tid & 3) << 2;      // A transposed load
    int lr = tid >> 4, lc = (tid & 15) << 2;      // B K-major load
    int ty = tid >> 4, tx = tid & 15;
    float acc[4][4] = {};
    for (int kb = 0; kb < KD; kb += 16) {
        float4 av = *(const float4*)&Ww[(size_t)(i0 + ai) * KD + kb + akq];
        As[akq + 0][ai] = av.x; As[akq + 1][ai] = av.y;
        As[akq + 2][ai] = av.z; As[akq + 3][ai] = av.w;
        *(float4*)&Bs[lr][lc] = *(const float4*)&Bmat[(size_t)(kb + lr) * KD + j0 + lc];
        __syncthreads();
#pragma unroll
        for (int k = 0; k < 16; k++) {
            float a[4], bb[4];
            *(float4*)a = *(const float4*)&As[k][ty * 4];
            *(float4*)bb = *(const float4*)&Bs[k][tx * 4];
#pragma unroll
            for (int ii = 0; ii < 4; ii++)
#pragma unroll
                for (int jj = 0; jj < 4; jj++) acc[ii][jj] += a[ii] * bb[jj];
        }
        __syncthreads();
    }
    float* C = g_M + (size_t)b * KD * KD;
    const float* sv = g_s + b * KD;
#pragma unroll
    for (int ii = 0; ii < 4; ii++) {
        float wbv = Wb[i0 + ty * 4 + ii];
        float4 v;
        v.x = acc[ii][0] + wbv * sv[j0 + tx * 4 + 0];
        v.y = acc[ii][1] + wbv * sv[j0 + tx * 4 + 1];
        v.z = acc[ii][2] + wbv * sv[j0 + tx * 4 + 2];
        v.w = acc[ii][3] + wbv * sv[j0 + tx * 4 + 3];
        *(float4*)&C[(size_t)(i0 + ty * 4 + ii) * KD + j0 + tx * 4] = v;
    }
}

// ---------------------------------------------------------------------------
// Generic 128x128 tile, 8x8/thread fp32 GEMM body
//  AM: 0 = A is K-major (K x M rows), 1 = A is M-major (M x K rows)
//  BM: 0 = B is K-major (K x N rows), 1 = B is N-major (N x K rows)
//  NB: bounds-check columns against Nlim; BIAS: add bias[j]
// ---------------------------------------------------------------------------
template <int AM, int BM, bool NB, bool BIAS>
__device__ __forceinline__ void gemm128_body(const float* __restrict__ A, int lda,
                                             const float* __restrict__ Bm, int ldb,
                                             float* __restrict__ C, int ldc, int K,
                                             int Nlim, const float* __restrict__ bias) {
    __shared__ float As[16][128];
    __shared__ float Bs[16][128];
    int i0 = blockIdx.x * 128, j0 = blockIdx.y * 128;
    int tid = threadIdx.x;
    int tx = tid & 15, ty = tid >> 4;
    float acc[8][8] = {};
    for (int kb = 0; kb < K; kb += 16) {
#pragma unroll
        for (int r = 0; r < 2; r++) {
            int idx = tid + r * 256;
            if (AM == 0) {
                int kr = idx >> 5, ic = (idx & 31) << 2;
                *(float4*)&As[kr][ic] = *(const float4*)&A[(size_t)(kb + kr) * lda + i0 + ic];
            } else {
                int i = idx >> 2, kq = (idx & 3) << 2;
                float4 v = *(const float4*)&A[(size_t)(i0 + i) * lda + kb + kq];
                As[kq + 0][i] = v.x; As[kq + 1][i] = v.y;
                As[kq + 2][i] = v.z; As[kq + 3][i] = v.w;
            }
            if (BM == 0) {
                int kr = idx >> 5, jc = (idx & 31) << 2;
                *(float4*)&Bs[kr][jc] = *(const float4*)&Bm[(size_t)(kb + kr) * ldb + j0 + jc];
            } else {
                int j = idx >> 2, kq = (idx & 3) << 2;
                float4 v = make_float4(0.f, 0.f, 0.f, 0.f);
                if (!NB || (j0 + j) < Nlim)
                    v = *(const float4*)&Bm[(size_t)(j0 + j) * ldb + kb + kq];
                Bs[kq + 0][j] = v.x; Bs[kq + 1][j] = v.y;
                Bs[kq + 2][j] = v.z; Bs[kq + 3][j] = v.w;
            }
        }
        __syncthreads();
#pragma unroll
        for (int k = 0; k < 16; k++) {
            float a[8], bb[8];
            *(float4*)&a[0] = *(const float4*)&As[k][ty * 8];
            *(float4*)&a[4] = *(const float4*)&As[k][ty * 8 + 4];
            *(float4*)&bb[0] = *(const float4*)&Bs[k][tx * 8];
            *(float4*)&bb[4] = *(const float4*)&Bs[k][tx * 8 + 4];
#pragma unroll
            for (int ii = 0; ii < 8; ii++)
#pragma unroll
                for (int jj = 0; jj < 8; jj++) acc[ii][jj] += a[ii] * bb[jj];
        }
        __syncthreads();
    }
#pragma unroll
    for (int ii = 0; ii < 8; ii++) {
        int i = i0 + ty * 8 + ii;
#pragma unroll
        for (int jq = 0; jq < 2; jq++) {
            int j = j0 + tx * 8 + jq * 4;
            if (NB && j >= Nlim) continue;  // Nlim multiple of 4 -> float4 safe
            float4 v;
            v.x = acc[ii][jq * 4 + 0];
            v.y = acc[ii][jq * 4 + 1];
            v.z = acc[ii][jq * 4 + 2];
            v.w = acc[ii][jq * 4 + 3];
            if (BIAS) {
                v.x += bias[j]; v.y += bias[j + 1];
                v.z += bias[j + 2]; v.w += bias[j + 3];
            }
            *(float4*)&C[(size_t)i * ldc + j] = v;
        }
    }
}

// y[b] = X * M[b] : A = x (M-major view, lda=KB*KD), B = M[b] (K-major)
__global__ __launch_bounds__(256) void gemm_y_k(const float* __restrict__ x) {
    int b = blockIdx.z;
    gemm128_body<1, 0, false, false>(x + b * KD, KB * KD, g_M + (size_t)b * KD * KD, KD,
                                     g_y + (size_t)b * KL * KD, KD, KD, KD, nullptr);
}

// logits[r] = y[r] * Lw^T + Lb : A = g_y (16384 x 512), B = Lw (V x D, N-major)
__global__ __launch_bounds__(256) void gemm_logits_k(const float* __restrict__ Lw,
                                                     const float* __restrict__ Lb) {
    gemm128_body<1, 1, true, true>(g_y, KD, Lw, KD, g_logits, KV, KD, KV, Lb);
}

// ---------------------------------------------------------------------------
// log_softmax over V + permute (B,L,V) -> (L,B,V); one block per row
// ---------------------------------------------------------------------------
__global__ void logsoftmax_k(float* __restrict__ out) {
    int l = blockIdx.x, b = blockIdx.y;
    const float* row = g_logits + (size_t)(b * KL + l) * KV;
    float* orow = out + (size_t)(l * KB + b) * KV;
    __shared__ float red[256];
    int t = threadIdx.x;
    float vals[4];
    float vmax = -3.4e38f;
#pragma unroll
    for (int r = 0; r < 4; r++) {
        int v = t + r * 256;
        vals[r] = (v < KV) ? row[v] : -3.4e38f;
        vmax = fmaxf(vmax, vals[r]);
    }
    red[t] = vmax;
    __syncthreads();
#pragma unroll
    for (int s = 128; s >= 1; s >>= 1) {
        if (t < s) red[t] = fmaxf(red[t], red[t + s]);
        __syncthreads();
    }
    vmax = red[0];
    __syncthreads();
    float se = 0.f;
#pragma unroll
    for (int r = 0; r < 4; r++) {
        int v = t + r * 256;
        if (v < KV) se += __expf(vals[r] - vmax);
    }
    red[t] = se;
    __syncthreads();
#pragma unroll
    for (int s = 128; s >= 1; s >>= 1) {
        if (t < s) red[t] += red[t + s];
        __syncthreads();
    }
    float denom = vmax + logf(red[0]);
#pragma unroll
    for (int r = 0; r < 4; r++) {
        int v = t + r * 256;
        if (v < KV) orow[v] = vals[r] - denom;
    }
}

// ---------------------------------------------------------------------------
extern "C" void kernel_launch(void* const* d_in, const int* in_sizes, int n_in,
                              void* d_out, int out_size) {
    (void)in_sizes; (void)n_in; (void)out_size;
    const float* x  = (const float*)d_in[0];
    const float* Ww = (const float*)d_in[1];
    const float* Wb = (const float*)d_in[2];
    const float* Lw = (const float*)d_in[3];
    const float* Lb = (const float*)d_in[4];
    float* out = (float*)d_out;

    colsum_part_k<<<dim3(16, KB), 256>>>(x);
    colsum_final_k<<<(KB * KD) / 256, 256>>>();
    gemm_G_k<<<dim3(KD / 64, KD / 64, KB), 256>>>(x);
    gemm_M_k<<<dim3(KD / 64, KD / 64, KB), 256>>>(Ww, Wb);
    gemm_y_k<<<dim3(KL / 128, KD / 128, KB), 256>>>(x);
    gemm_logits_k<<<dim3((KL * KB) / 128, (KV + 127) / 128), 256>>>(Lw, Lb);
    logsoftmax_k<<<dim3(KL, KB), 256>>>(out);
}

// round 3
// speedup vs baseline: 2.3931x; 2.3931x over previous
#include <cuda_runtime.h>
#include <cuda_bf16.h>
#include <cstdint>

#define KL 4096
#define KB 4
#define KD 512
#define KV 1000
#define KVP 1024   // padded vocab

// ---------------------------------------------------------------------------
// PTX helpers (sm_80-compatible only: ldmatrix / mma.sync / cp.async)
// ---------------------------------------------------------------------------
__device__ __forceinline__ uint32_t smem_to_u32(const void* p) {
    uint32_t a;
    asm("{ .reg .u64 t; cvta.to.shared.u64 t, %1; cvt.u32.u64 %0, t; }" : "=r"(a) : "l"(p));
    return a;
}
__device__ __forceinline__ void cpasync16(uint32_t s, const void* g) {
    asm volatile("cp.async.cg.shared.global [%0], [%1], 16;" :: "r"(s), "l"(g));
}
__device__ __forceinline__ void cp_commit() {
    asm volatile("cp.async.commit_group;" ::: "memory");
}
template <int N>
__device__ __forceinline__ void cp_wait() {
    asm volatile("cp.async.wait_group %0;" :: "n"(N) : "memory");
}
__device__ __forceinline__ void ldmx4(uint32_t* r, uint32_t a) {
    asm volatile("ldmatrix.sync.aligned.m8n8.x4.shared.b16 {%0,%1,%2,%3}, [%4];"
                 : "=r"(r[0]), "=r"(r[1]), "=r"(r[2]), "=r"(r[3]) : "r"(a));
}
__device__ __forceinline__ void mma16816(float* d, const uint32_t* a, const uint32_t* b) {
    asm volatile(
        "mma.sync.aligned.m16n8k16.row.col.f32.bf16.bf16.f32 "
        "{%0,%1,%2,%3}, {%4,%5,%6,%7}, {%8,%9}, {%0,%1,%2,%3};"
        : "+f"(d[0]), "+f"(d[1]), "+f"(d[2]), "+f"(d[3])
        : "r"(a[0]), "r"(a[1]), "r"(a[2]), "r"(a[3]), "r"(b[0]), "r"(b[1]));
}
#define SMEM_SWIZZLE_128B(o) ((o) ^ (((o) >> 3) & 0x70))

// ---------------------------------------------------------------------------
// scratch (static device globals; no allocations)
// ---------------------------------------------------------------------------
__device__ __align__(128) float g_part[KB * 16 * KD];
__device__ __align__(128) float g_s[KB * KD];
__device__ __align__(128) __nv_bfloat16 g_Xb_hi[(size_t)KB * KL * KD], g_Xb_lo[(size_t)KB * KL * KD];
__device__ __align__(128) __nv_bfloat16 g_Xt_hi[(size_t)KB * KD * KL], g_Xt_lo[(size_t)KB * KD * KL];
__device__ __align__(128) __nv_bfloat16 g_Ww_hi[KD * KD], g_Ww_lo[KD * KD];
__device__ __align__(128) __nv_bfloat16 g_Lw_hi[KVP * KD], g_Lw_lo[KVP * KD];
__device__ __align__(128) float g_Lbp[KVP];
__device__ __align__(128) __nv_bfloat16 g_G_hi[KB * KD * KD], g_G_lo[KB * KD * KD];
__device__ __align__(128) __nv_bfloat16 g_Mt_hi[KB * KD * KD], g_Mt_lo[KB * KD * KD];
__device__ __align__(128) __nv_bfloat16 g_y_hi[(size_t)KB * KL * KD], g_y_lo[(size_t)KB * KL * KD];
__device__ __align__(128) float g_logits[(size_t)KB * KL * KVP];

__device__ __forceinline__ void split_f32(float v, __nv_bfloat16& h, __nv_bfloat16& l) {
    h = __float2bfloat16(v);
    l = __float2bfloat16(v - __bfloat162float(h));
}

// ---------------------------------------------------------------------------
// column sums of x over l
// ---------------------------------------------------------------------------
__global__ void colsum_part_k(const float* __restrict__ x) {
    int b = blockIdx.y, slab = blockIdx.x;
    int d = threadIdx.x;
    const float* base = x + b * KD;
    float s0 = 0.f, s1 = 0.f;
    int l0 = slab * (KL / 16);
#pragma unroll 4
    for (int l = l0; l < l0 + (KL / 16); ++l) {
        s0 += base[(size_t)l * (KB * KD) + d];
        s1 += base[(size_t)l * (KB * KD) + d + 256];
    }
    g_part[(b * 16 + slab) * KD + d] = s0;
    g_part[(b * 16 + slab) * KD + d + 256] = s1;
}
__global__ void colsum_final_k() {
    int idx = blockIdx.x * 256 + threadIdx.x;
    float s = 0.f;
#pragma unroll
    for (int k = 0; k < 16; k++) s += g_part[(idx / KD * 16 + k) * KD + idx % KD];
    g_s[idx] = s;
}

// ---------------------------------------------------------------------------
// prep_x: x (L,B,D) fp32 -> Xb[b][l][d] hi/lo  and  Xt[b][d][l] hi/lo
// ---------------------------------------------------------------------------
__global__ __launch_bounds__(256) void prep_x_k(const float* __restrict__ x) {
    __shared__ __nv_bfloat16 shi[64][65], slo[64][65];
    int b = blockIdx.z;
    int l0 = blockIdx.x * 64, d0 = blockIdx.y * 64;
    int t = threadIdx.x;
    int c = t & 63, r4 = t >> 6;
#pragma unroll 4
    for (int rr = 0; rr < 16; rr++) {
        int r = r4 * 16 + rr;
        float v = x[(size_t)(l0 + r) * (KB * KD) + b * KD + d0 + c];
        __nv_bfloat16 h, l;
        split_f32(v, h, l);
        size_t o = ((size_t)b * KL + (l0 + r)) * KD + d0 + c;
        g_Xb_hi[o] = h; g_Xb_lo[o] = l;
        shi[r][c] = h; slo[r][c] = l;
    }
    __syncthreads();
#pragma unroll 4
    for (int rr = 0; rr < 16; rr++) {
        int r = r4 * 16 + rr;   // d index
        size_t o = ((size_t)b * KD + (d0 + r)) * KL + l0 + c;
        g_Xt_hi[o] = shi[c][r];
        g_Xt_lo[o] = slo[c][r];
    }
}

// ---------------------------------------------------------------------------
// prep_w: split Ww; split Lw padded to 1024 rows; pad Lb
// ---------------------------------------------------------------------------
__global__ void prep_w_k(const float* __restrict__ Ww, const float* __restrict__ Lw,
                         const float* __restrict__ Lb) {
    int row = blockIdx.x;
    int t = threadIdx.x;
    for (int c = t; c < KD; c += 256) {
        if (row < KD) {
            __nv_bfloat16 h, l;
            split_f32(Ww[row * KD + c], h, l);
            g_Ww_hi[row * KD + c] = h; g_Ww_lo[row * KD + c] = l;
        }
        float v2 = (row < KV) ? Lw[row * KD + c] : 0.f;
        __nv_bfloat16 h2, l2;
        split_f32(v2, h2, l2);
        g_Lw_hi[row * KD + c] = h2; g_Lw_lo[row * KD + c] = l2;
    }
    if (row == 0)
        for (int c = t; c < KVP; c += 256) g_Lbp[c] = (c < KV) ? Lb[c] : 0.f;
}

// ---------------------------------------------------------------------------
// mma.sync bf16 split GEMM: C[m][n] = sum_k A[m][k]*B[n][k], hi/lo 3-product
//   A: [Mrows, K] bf16 K-major, batch stride sA ; B likewise (sB)
//   mode 0: write Chi/Clo bf16
//   mode 1: + eu[row]*ev[col] rank-1, write Chi/Clo
//   mode 2: + ev[col] bias, write Cf fp32
// CTA tile 128x128, K-chunk 64, 2-stage cp.async pipeline, 8 warps (64x32).
// ---------------------------------------------------------------------------
#define TILE_BYTES 16384               // 128 rows x 128B (64 bf16)
#define STAGE_BYTES (4 * TILE_BYTES)   // Ah, Al, Bh, Bl
#define DYN_SMEM (2 * STAGE_BYTES)     // 128 KB

__global__ __launch_bounds__(256, 1) void mma_gemm_k(
    const __nv_bfloat16* __restrict__ Ahi, const __nv_bfloat16* __restrict__ Alo, size_t sA,
    const __nv_bfloat16* __restrict__ Bhi, const __nv_bfloat16* __restrict__ Blo, size_t sB,
    int K,
    __nv_bfloat16* __restrict__ Chi, __nv_bfloat16* __restrict__ Clo,
    float* __restrict__ Cf, size_t sC, int ldc,
    const float* __restrict__ eu, size_t sU, const float* __restrict__ ev, int mode) {
    extern __shared__ __align__(1024) char smem[];
    uint32_t smb = smem_to_u32(smem);
    int tid = threadIdx.x;
    int wid = tid >> 5, lane = tid & 31;
    int bz = blockIdx.z;
    int i0 = blockIdx.x * 128, j0 = blockIdx.y * 128;
    int wm = (wid >> 2) * 64, wn = (wid & 3) * 32;

    const __nv_bfloat16* tiles[4] = {Ahi + sA * bz, Alo + sA * bz, Bhi + sB * bz, Blo + sB * bz};
    const int row0[4] = {i0, i0, j0, j0};
    const int NC = K >> 6;

    // precomputed loader indices: 4 iters x (r,u)
    int lr[4], lu[4];
#pragma unroll
    for (int it = 0; it < 4; it++) {
        int q = tid + it * 256;
        lr[it] = q >> 3;
        lu[it] = q & 7;
    }

    auto load_chunk = [&](int koff, int st) {
        uint32_t sbase = smb + st * STAGE_BYTES;
#pragma unroll
        for (int tile = 0; tile < 4; tile++) {
            const __nv_bfloat16* src = tiles[tile];
#pragma unroll
            for (int it = 0; it < 4; it++) {
                uint32_t boff = (uint32_t)(lr[it] * 128 + lu[it] * 16);
                uint32_t sw = SMEM_SWIZZLE_128B(boff);
                const void* g = src + (size_t)(row0[tile] + lr[it]) * K + koff + lu[it] * 8;
                cpasync16(sbase + tile * TILE_BYTES + sw, g);
            }
        }
        cp_commit();
    };

    float acc[4][4][4];
#pragma unroll
    for (int a = 0; a < 4; a++)
#pragma unroll
        for (int b = 0; b < 4; b++)
#pragma unroll
            for (int c = 0; c < 4; c++) acc[a][b][c] = 0.f;

    // fragment address components (byte offsets within a tile, pre-swizzle)
    int arow = wm + (lane & 15);
    int akh16 = ((lane >> 4) & 1) * 16;
    int brow = wn + ((lane >> 4) & 1) * 8 + (lane & 7);
    int bkh16 = ((lane >> 3) & 1) * 16;

    load_chunk(0, 0);

    for (int kc = 0; kc < NC; kc++) {
        int st = kc & 1;
        if (kc + 1 < NC) {
            load_chunk((kc + 1) << 6, st ^ 1);
            cp_wait<1>();
        } else {
            cp_wait<0>();
        }
        __syncthreads();

        uint32_t sAh = smb + st * STAGE_BYTES;
        uint32_t sAl = sAh + TILE_BYTES;
        uint32_t sBh = sAh + 2 * TILE_BYTES;
        uint32_t sBl = sAh + 3 * TILE_BYTES;

#pragma unroll
        for (int kk = 0; kk < 4; kk++) {
            uint32_t ah[4][4], al[4][4], bh[2][4], bl[2][4];
#pragma unroll
            for (int mt = 0; mt < 4; mt++) {
                uint32_t o = (uint32_t)((arow + mt * 16) * 128 + kk * 32 + akh16);
                uint32_t sw = SMEM_SWIZZLE_128B(o);
                ldmx4(ah[mt], sAh + sw);
                ldmx4(al[mt], sAl + sw);
            }
#pragma unroll
            for (int np = 0; np < 2; np++) {
                uint32_t o = (uint32_t)((brow + np * 16) * 128 + kk * 32 + bkh16);
                uint32_t sw = SMEM_SWIZZLE_128B(o);
                ldmx4(bh[np], sBh + sw);
                ldmx4(bl[np], sBl + sw);
            }
#pragma unroll
            for (int mt = 0; mt < 4; mt++)
#pragma unroll
                for (int nt = 0; nt < 4; nt++) {
                    uint32_t* bfh = &bh[nt >> 1][(nt & 1) * 2];
                    uint32_t* bfl = &bl[nt >> 1][(nt & 1) * 2];
                    mma16816(acc[mt][nt], ah[mt], bfh);  // hi*hi
                    mma16816(acc[mt][nt], ah[mt], bfl);  // hi*lo
                    mma16816(acc[mt][nt], al[mt], bfh);  // lo*hi
                }
        }
        __syncthreads();
    }

    // ---- epilogue ----
#pragma unroll
    for (int mt = 0; mt < 4; mt++) {
#pragma unroll
        for (int half = 0; half < 2; half++) {
            int row = i0 + wm + mt * 16 + (lane >> 2) + half * 8;
            float uval = (mode == 1) ? eu[sU * bz + row] : 0.f;
#pragma unroll
            for (int nt = 0; nt < 4; nt++) {
                int c0 = j0 + wn + nt * 8 + (lane & 3) * 2;
                float v0 = acc[mt][nt][half * 2 + 0];
                float v1 = acc[mt][nt][half * 2 + 1];
                if (mode == 1) {
                    v0 += uval * ev[c0];
                    v1 += uval * ev[c0 + 1];
                }
                if (mode == 2) {
                    float2 f2 = make_float2(v0 + ev[c0], v1 + ev[c0 + 1]);
                    *(float2*)&Cf[sC * bz + (size_t)row * ldc + c0] = f2;
                } else {
                    __nv_bfloat162 h2, l2;
                    split_f32(v0, h2.x, l2.x);
                    split_f32(v1, h2.y, l2.y);
                    *(__nv_bfloat162*)&Chi[sC * bz + (size_t)row * ldc + c0] = h2;
                    *(__nv_bfloat162*)&Clo[sC * bz + (size_t)row * ldc + c0] = l2;
                }
            }
        }
    }
}

// ---------------------------------------------------------------------------
// log_softmax over V + permute (B,L,V)->(L,B,V); logits ld = KVP
// ---------------------------------------------------------------------------
__global__ void logsoftmax_k(float* __restrict__ out) {
    int l = blockIdx.x, b = blockIdx.y;
    const float* row = g_logits + (size_t)(b * KL + l) * KVP;
    float* orow = out + (size_t)(l * KB + b) * KV;
    __shared__ float red[256];
    int t = threadIdx.x;
    float vals[4];
    float vmax = -3.4e38f;
#pragma unroll
    for (int r = 0; r < 4; r++) {
        int v = t + r * 256;
        vals[r] = (v < KV) ? row[v] : -3.4e38f;
        vmax = fmaxf(vmax, vals[r]);
    }
    red[t] = vmax;
    __syncthreads();
#pragma unroll
    for (int s = 128; s >= 1; s >>= 1) {
        if (t < s) red[t] = fmaxf(red[t], red[t + s]);
        __syncthreads();
    }
    vmax = red[0];
    __syncthreads();
    float se = 0.f;
#pragma unroll
    for (int r = 0; r < 4; r++) {
        int v = t + r * 256;
        if (v < KV) se += __expf(vals[r] - vmax);
    }
    red[t] = se;
    __syncthreads();
#pragma unroll
    for (int s = 128; s >= 1; s >>= 1) {
        if (t < s) red[t] += red[t + s];
        __syncthreads();
    }
    float denom = vmax + logf(red[0]);
#pragma unroll
    for (int r = 0; r < 4; r++) {
        int v = t + r * 256;
        if (v < KV) orow[v] = vals[r] - denom;
    }
}

// ---------------------------------------------------------------------------
extern "C" void kernel_launch(void* const* d_in, const int* in_sizes, int n_in,
                              void* d_out, int out_size) {
    (void)in_sizes; (void)n_in; (void)out_size;
    const float* x  = (const float*)d_in[0];
    const float* Ww = (const float*)d_in[1];
    const float* Wb = (const float*)d_in[2];
    const float* Lw = (const float*)d_in[3];
    const float* Lb = (const float*)d_in[4];
    float* out = (float*)d_out;

    static bool attr_set = false;
    if (!attr_set) {
        cudaFuncSetAttribute(mma_gemm_k, cudaFuncAttributeMaxDynamicSharedMemorySize, DYN_SMEM);
        attr_set = true;
    }

    __nv_bfloat16 *Xb_hi, *Xb_lo, *Xt_hi, *Xt_lo, *Wwh, *Wwl, *Lwh, *Lwl;
    __nv_bfloat16 *Gh, *Gl, *Mth, *Mtl, *yh, *yl;
    float *sptr, *Lbp, *logits;
    cudaGetSymbolAddress((void**)&Xb_hi, g_Xb_hi);
    cudaGetSymbolAddress((void**)&Xb_lo, g_Xb_lo);
    cudaGetSymbolAddress((void**)&Xt_hi, g_Xt_hi);
    cudaGetSymbolAddress((void**)&Xt_lo, g_Xt_lo);
    cudaGetSymbolAddress((void**)&Wwh, g_Ww_hi);
    cudaGetSymbolAddress((void**)&Wwl, g_Ww_lo);
    cudaGetSymbolAddress((void**)&Lwh, g_Lw_hi);
    cudaGetSymbolAddress((void**)&Lwl, g_Lw_lo);
    cudaGetSymbolAddress((void**)&Gh, g_G_hi);
    cudaGetSymbolAddress((void**)&Gl, g_G_lo);
    cudaGetSymbolAddress((void**)&Mth, g_Mt_hi);
    cudaGetSymbolAddress((void**)&Mtl, g_Mt_lo);
    cudaGetSymbolAddress((void**)&yh, g_y_hi);
    cudaGetSymbolAddress((void**)&yl, g_y_lo);
    cudaGetSymbolAddress((void**)&sptr, g_s);
    cudaGetSymbolAddress((void**)&Lbp, g_Lbp);
    cudaGetSymbolAddress((void**)&logits, g_logits);

    colsum_part_k<<<dim3(16, KB), 256>>>(x);
    colsum_final_k<<<(KB * KD) / 256, 256>>>();
    prep_x_k<<<dim3(KL / 64, KD / 64, KB), 256>>>(x);
    prep_w_k<<<KVP, 256>>>(Ww, Lw, Lb);

    // G[b] = Xt * Xt^T   (512x512, K=4096)
    mma_gemm_k<<<dim3(4, 4, KB), 256, DYN_SMEM>>>(
        Xt_hi, Xt_lo, (size_t)KD * KL, Xt_hi, Xt_lo, (size_t)KD * KL, KL,
        Gh, Gl, nullptr, (size_t)KD * KD, KD, nullptr, 0, nullptr, 0);

    // Mt[b] = G * Ww^T + s (x) Wb   (512x512, K=512)
    mma_gemm_k<<<dim3(4, 4, KB), 256, DYN_SMEM>>>(
        Gh, Gl, (size_t)KD * KD, Wwh, Wwl, 0, KD,
        Mth, Mtl, nullptr, (size_t)KD * KD, KD, sptr, KD, Wb, 1);

    // y[b] = Xb * Mt^T   (4096x512, K=512)
    mma_gemm_k<<<dim3(32, 4, KB), 256, DYN_SMEM>>>(
        Xb_hi, Xb_lo, (size_t)KL * KD, Mth, Mtl, (size_t)KD * KD, KD,
        yh, yl, nullptr, (size_t)KL * KD, KD, nullptr, 0, nullptr, 0);

    // logits = y * Lw^T + Lb   (16384 x 1024, K=512)
    mma_gemm_k<<<dim3(128, 8, 1), 256, DYN_SMEM>>>(
        yh, yl, 0, Lwh, Lwl, 0, KD,
        nullptr, nullptr, logits, 0, KVP, nullptr, 0, Lbp, 2);

    logsoftmax_k<<<dim3(KL, KB), 256>>>(out);
}

// round 4
// speedup vs baseline: 3.1672x; 1.3235x over previous
#include <cuda_runtime.h>
#include <cuda_bf16.h>
#include <cstdint>

#define KL 4096
#define KB 4
#define KD 512
#define KV 1000
#define KVP 1024   // padded vocab

// ---------------------------------------------------------------------------
// PTX helpers (sm_80-compatible only: ldmatrix / mma.sync / cp.async)
// ---------------------------------------------------------------------------
__device__ __forceinline__ uint32_t smem_to_u32(const void* p) {
    uint32_t a;
    asm("{ .reg .u64 t; cvta.to.shared.u64 t, %1; cvt.u32.u64 %0, t; }" : "=r"(a) : "l"(p));
    return a;
}
__device__ __forceinline__ void cpasync16(uint32_t s, const void* g) {
    asm volatile("cp.async.cg.shared.global [%0], [%1], 16;" :: "r"(s), "l"(g));
}
__device__ __forceinline__ void cp_commit() {
    asm volatile("cp.async.commit_group;" ::: "memory");
}
template <int N>
__device__ __forceinline__ void cp_wait() {
    asm volatile("cp.async.wait_group %0;" :: "n"(N) : "memory");
}
__device__ __forceinline__ void ldmx4(uint32_t* r, uint32_t a) {
    asm volatile("ldmatrix.sync.aligned.m8n8.x4.shared.b16 {%0,%1,%2,%3}, [%4];"
                 : "=r"(r[0]), "=r"(r[1]), "=r"(r[2]), "=r"(r[3]) : "r"(a));
}
__device__ __forceinline__ void mma16816(float* d, const uint32_t* a, const uint32_t* b) {
    asm volatile(
        "mma.sync.aligned.m16n8k16.row.col.f32.bf16.bf16.f32 "
        "{%0,%1,%2,%3}, {%4,%5,%6,%7}, {%8,%9}, {%0,%1,%2,%3};"
        : "+f"(d[0]), "+f"(d[1]), "+f"(d[2]), "+f"(d[3])
        : "r"(a[0]), "r"(a[1]), "r"(a[2]), "r"(a[3]), "r"(b[0]), "r"(b[1]));
}
#define SMEM_SWIZZLE_128B(o) ((o) ^ (((o) >> 3) & 0x70))

// ---------------------------------------------------------------------------
// scratch (static device globals; no allocations)
// ---------------------------------------------------------------------------
__device__ __align__(128) float g_part2[KB * KD * 64];   // per-(l-slab) colsum partials
__device__ __align__(128) float g_s[KB * KD];
__device__ __align__(128) __nv_bfloat16 g_Xb_hi[(size_t)KB * KL * KD], g_Xb_lo[(size_t)KB * KL * KD];
__device__ __align__(128) __nv_bfloat16 g_Xt_hi[(size_t)KB * KD * KL], g_Xt_lo[(size_t)KB * KD * KL];
__device__ __align__(128) __nv_bfloat16 g_Ww_hi[KD * KD], g_Ww_lo[KD * KD];
__device__ __align__(128) __nv_bfloat16 g_Lw_hi[KVP * KD], g_Lw_lo[KVP * KD];
__device__ __align__(128) float g_Lbp[KVP];
__device__ __align__(128) float g_Gp[2 * KB * KD * KD];   // G K-split partials (8 MB)
__device__ __align__(128) float g_Mtp[4 * KB * KD * KD];  // Mt K-split partials (16 MB)
__device__ __align__(128) __nv_bfloat16 g_G_hi[KB * KD * KD], g_G_lo[KB * KD * KD];
__device__ __align__(128) __nv_bfloat16 g_Mt_hi[KB * KD * KD], g_Mt_lo[KB * KD * KD];
__device__ __align__(128) __nv_bfloat16 g_y_hi[(size_t)KB * KL * KD], g_y_lo[(size_t)KB * KL * KD];
__device__ __align__(128) float g_logits[(size_t)KB * KL * KVP];

__device__ __forceinline__ void split_f32(float v, __nv_bfloat16& h, __nv_bfloat16& l) {
    h = __float2bfloat16(v);
    l = __float2bfloat16(v - __bfloat162float(h));
}

// ---------------------------------------------------------------------------
// prep_x: x (L,B,D) fp32 -> Xb[b][l][d] hi/lo, Xt[b][d][l] hi/lo, colsum partials
// ---------------------------------------------------------------------------
__global__ __launch_bounds__(256) void prep_x_k(const float* __restrict__ x) {
    __shared__ __nv_bfloat16 shi[64][65], slo[64][65];
    __shared__ float ssum[4][64];
    int b = blockIdx.z;
    int lblk = blockIdx.x;
    int l0 = lblk * 64, d0 = blockIdx.y * 64;
    int t = threadIdx.x;
    int c = t & 63, r4 = t >> 6;
    float ps = 0.f;
#pragma unroll 4
    for (int rr = 0; rr < 16; rr++) {
        int r = r4 * 16 + rr;
        float v = x[(size_t)(l0 + r) * (KB * KD) + b * KD + d0 + c];
        ps += v;
        __nv_bfloat16 h, l;
        split_f32(v, h, l);
        size_t o = ((size_t)b * KL + (l0 + r)) * KD + d0 + c;
        g_Xb_hi[o] = h; g_Xb_lo[o] = l;
        shi[r][c] = h; slo[r][c] = l;
    }
    ssum[r4][c] = ps;
    __syncthreads();
#pragma unroll 4
    for (int rr = 0; rr < 16; rr++) {
        int r = r4 * 16 + rr;   // d index
        size_t o = ((size_t)b * KD + (d0 + r)) * KL + l0 + c;
        g_Xt_hi[o] = shi[c][r];
        g_Xt_lo[o] = slo[c][r];
    }
    if (t < 64) {
        float s = ssum[0][t] + ssum[1][t] + ssum[2][t] + ssum[3][t];
        g_part2[((size_t)b * KD + d0 + t) * 64 + lblk] = s;
    }
}

__global__ void colsum_final_k() {
    int idx = blockIdx.x * 256 + threadIdx.x;  // KB*KD
    float s = 0.f;
    const float* p = &g_part2[(size_t)idx * 64];
#pragma unroll
    for (int k = 0; k < 64; k++) s += p[k];
    g_s[idx] = s;
}

// ---------------------------------------------------------------------------
// prep_w: split Ww; split Lw padded to 1024 rows; pad Lb
// ---------------------------------------------------------------------------
__global__ void prep_w_k(const float* __restrict__ Ww, const float* __restrict__ Lw,
                         const float* __restrict__ Lb) {
    int row = blockIdx.x;
    int t = threadIdx.x;
    for (int c = t; c < KD; c += 256) {
        if (row < KD) {
            __nv_bfloat16 h, l;
            split_f32(Ww[row * KD + c], h, l);
            g_Ww_hi[row * KD + c] = h; g_Ww_lo[row * KD + c] = l;
        }
        float v2 = (row < KV) ? Lw[row * KD + c] : 0.f;
        __nv_bfloat16 h2, l2;
        split_f32(v2, h2, l2);
        g_Lw_hi[row * KD + c] = h2; g_Lw_lo[row * KD + c] = l2;
    }
    if (row == 0)
        for (int c = t; c < KVP; c += 256) g_Lbp[c] = (c < KV) ? Lb[c] : 0.f;
}

// ---------------------------------------------------------------------------
// mma.sync bf16 split GEMM: C[m][n] = sum_k A[m][k]*B[n][k], hi/lo 3-product
//   A: [Mrows, ldk] bf16 K-major, batch stride sA ; B likewise (sB)
//   K-split: blockIdx.z = b*nsplit + sp; chunk k offsets start at sp*Kiter
//   mode 0: write Chi/Clo bf16 (at batch b)
//   mode 2: write Cf fp32 + bias[col] (at batch b)
//   mode 3: write Cf fp32 partial (at slot blockIdx.z)
// CTA tile 128x128, K-chunk 64, 3-stage cp.async pipeline, 8 warps (64x32).
// ---------------------------------------------------------------------------
#define TILE_BYTES 16384               // 128 rows x 128B (64 bf16)
#define STAGE_BYTES (4 * TILE_BYTES)   // Ah, Al, Bh, Bl
#define NSTAGE 3
#define DYN_SMEM (NSTAGE * STAGE_BYTES)  // 192 KB

__global__ __launch_bounds__(256, 1) void mma_gemm_k(
    const __nv_bfloat16* __restrict__ Ahi, const __nv_bfloat16* __restrict__ Alo, size_t sA,
    const __nv_bfloat16* __restrict__ Bhi, const __nv_bfloat16* __restrict__ Blo, size_t sB,
    int ldk, int Kiter, int nsplit,
    __nv_bfloat16* __restrict__ Chi, __nv_bfloat16* __restrict__ Clo,
    float* __restrict__ Cf, size_t sC, int ldc,
    const float* __restrict__ bias, int mode) {
    extern __shared__ __align__(1024) char smem[];
    uint32_t smb = smem_to_u32(smem);
    int tid = threadIdx.x;
    int wid = tid >> 5, lane = tid & 31;
    int b = blockIdx.z / nsplit, sp = blockIdx.z % nsplit;
    int koff0 = sp * Kiter;
    int i0 = blockIdx.x * 128, j0 = blockIdx.y * 128;
    int wm = (wid >> 2) * 64, wn = (wid & 3) * 32;

    const __nv_bfloat16* tiles[4] = {Ahi + sA * b, Alo + sA * b, Bhi + sB * b, Blo + sB * b};
    const int row0[4] = {i0, i0, j0, j0};
    const int NC = Kiter >> 6;

    int lr[4], lu[4];
#pragma unroll
    for (int it = 0; it < 4; it++) {
        int q = tid + it * 256;
        lr[it] = q >> 3;
        lu[it] = q & 7;
    }

    auto load_chunk = [&](int chunk) {
        uint32_t sbase = smb + (chunk % NSTAGE) * STAGE_BYTES;
        int koff = koff0 + (chunk << 6);
#pragma unroll
        for (int tile = 0; tile < 4; tile++) {
            const __nv_bfloat16* src = tiles[tile];
#pragma unroll
            for (int it = 0; it < 4; it++) {
                uint32_t boff = (uint32_t)(lr[it] * 128 + lu[it] * 16);
                uint32_t sw = SMEM_SWIZZLE_128B(boff);
                const void* g = src + (size_t)(row0[tile] + lr[it]) * ldk + koff + lu[it] * 8;
                cpasync16(sbase + tile * TILE_BYTES + sw, g);
            }
        }
        cp_commit();
    };

    float acc[4][4][4];
#pragma unroll
    for (int a = 0; a < 4; a++)
#pragma unroll
        for (int bb = 0; bb < 4; bb++)
#pragma unroll
            for (int c = 0; c < 4; c++) acc[a][bb][c] = 0.f;

    int arow = wm + (lane & 15);
    int akh16 = ((lane >> 4) & 1) * 16;
    int brow = wn + ((lane >> 4) & 1) * 8 + (lane & 7);
    int bkh16 = ((lane >> 3) & 1) * 16;

    load_chunk(0);
    if (NC > 1) load_chunk(1);

    for (int kc = 0; kc < NC; kc++) {
        if (kc + 2 < NC) {
            load_chunk(kc + 2);
            cp_wait<2>();
        } else if (kc + 1 < NC) {
            cp_wait<1>();
        } else {
            cp_wait<0>();
        }
        __syncthreads();

        uint32_t sAh = smb + (kc % NSTAGE) * STAGE_BYTES;
        uint32_t sAl = sAh + TILE_BYTES;
        uint32_t sBh = sAh + 2 * TILE_BYTES;
        uint32_t sBl = sAh + 3 * TILE_BYTES;

#pragma unroll
        for (int kk = 0; kk < 4; kk++) {
            uint32_t ah[4][4], al[4][4], bh[2][4], bl[2][4];
#pragma unroll
            for (int mt = 0; mt < 4; mt++) {
                uint32_t o = (uint32_t)((arow + mt * 16) * 128 + kk * 32 + akh16);
                uint32_t sw = SMEM_SWIZZLE_128B(o);
                ldmx4(ah[mt], sAh + sw);
                ldmx4(al[mt], sAl + sw);
            }
#pragma unroll
            for (int np = 0; np < 2; np++) {
                uint32_t o = (uint32_t)((brow + np * 16) * 128 + kk * 32 + bkh16);
                uint32_t sw = SMEM_SWIZZLE_128B(o);
                ldmx4(bh[np], sBh + sw);
                ldmx4(bl[np], sBl + sw);
            }
#pragma unroll
            for (int mt = 0; mt < 4; mt++)
#pragma unroll
                for (int nt = 0; nt < 4; nt++) {
                    uint32_t* bfh = &bh[nt >> 1][(nt & 1) * 2];
                    uint32_t* bfl = &bl[nt >> 1][(nt & 1) * 2];
                    mma16816(acc[mt][nt], ah[mt], bfh);  // hi*hi
                    mma16816(acc[mt][nt], ah[mt], bfl);  // hi*lo
                    mma16816(acc[mt][nt], al[mt], bfh);  // lo*hi
                }
        }
        __syncthreads();
    }

    // ---- epilogue ----
#pragma unroll
    for (int mt = 0; mt < 4; mt++) {
#pragma unroll
        for (int half = 0; half < 2; half++) {
            int row = i0 + wm + mt * 16 + (lane >> 2) + half * 8;
#pragma unroll
            for (int nt = 0; nt < 4; nt++) {
                int c0 = j0 + wn + nt * 8 + (lane & 3) * 2;
                float v0 = acc[mt][nt][half * 2 + 0];
                float v1 = acc[mt][nt][half * 2 + 1];
                if (mode == 3) {
                    *(float2*)&Cf[sC * blockIdx.z + (size_t)row * ldc + c0] = make_float2(v0, v1);
                } else if (mode == 2) {
                    float2 f2 = make_float2(v0 + bias[c0], v1 + bias[c0 + 1]);
                    *(float2*)&Cf[sC * b + (size_t)row * ldc + c0] = f2;
                } else {
                    __nv_bfloat162 h2, l2;
                    split_f32(v0, h2.x, l2.x);
                    split_f32(v1, h2.y, l2.y);
                    *(__nv_bfloat162*)&Chi[sC * b + (size_t)row * ldc + c0] = h2;
                    *(__nv_bfloat162*)&Clo[sC * b + (size_t)row * ldc + c0] = l2;
                }
            }
        }
    }
}

// ---------------------------------------------------------------------------
// reduce K-split partials -> hi/lo bf16, optional rank-1 (eu[row]*ev[col])
// Layout: part[(b*nsplit+sp)*KD*KD + i*KD + j]; out[b*KD*KD + i*KD + j]
// ---------------------------------------------------------------------------
__global__ void reduce_split_k(const float* __restrict__ part, int nsplit,
                               __nv_bfloat16* __restrict__ hi, __nv_bfloat16* __restrict__ lo,
                               const float* __restrict__ eu, const float* __restrict__ ev,
                               int rank1) {
    size_t idx = ((size_t)blockIdx.x * 256 + threadIdx.x) * 2;  // over KB*KD*KD
    const size_t per = (size_t)KD * KD;
    int b = (int)(idx / per);
    size_t rem = idx % per;
    int i = (int)(rem / KD), j = (int)(rem % KD);
    float s0 = 0.f, s1 = 0.f;
    for (int sp = 0; sp < nsplit; sp++) {
        const float* p = part + ((size_t)(b * nsplit + sp)) * per + rem;
        s0 += p[0];
        s1 += p[1];
    }
    if (rank1) {
        float u = eu[b * KD + i];
        s0 += u * ev[j];
        s1 += u * ev[j + 1];
    }
    __nv_bfloat162 h2, l2;
    split_f32(s0, h2.x, l2.x);
    split_f32(s1, h2.y, l2.y);
    *(__nv_bfloat162*)&hi[idx] = h2;
    *(__nv_bfloat162*)&lo[idx] = l2;
}

// ---------------------------------------------------------------------------
// log_softmax over V + permute (B,L,V)->(L,B,V); warp-shuffle reductions
// ---------------------------------------------------------------------------
__global__ void logsoftmax_k(float* __restrict__ out) {
    int l = blockIdx.x, b = blockIdx.y;
    const float* row = g_logits + (size_t)(b * KL + l) * KVP;
    float* orow = out + (size_t)(l * KB + b) * KV;
    __shared__ float sred[8];
    int t = threadIdx.x;
    int wid = t >> 5, lane = t & 31;
    bool act = t < (KV / 4);   // 250 threads hold data
    float4 v = act ? *(const float4*)&row[t * 4]
                   : make_float4(-3.4e38f, -3.4e38f, -3.4e38f, -3.4e38f);
    float m = fmaxf(fmaxf(v.x, v.y), fmaxf(v.z, v.w));
#pragma unroll
    for (int s = 16; s >= 1; s >>= 1) m = fmaxf(m, __shfl_xor_sync(0xffffffffu, m, s));
    if (lane == 0) sred[wid] = m;
    __syncthreads();
    float m8 = (lane < 8) ? sred[lane] : -3.4e38f;
#pragma unroll
    for (int s = 4; s >= 1; s >>= 1) m8 = fmaxf(m8, __shfl_xor_sync(0xffffffffu, m8, s));
    float vmax = __shfl_sync(0xffffffffu, m8, 0);

    float e = act ? (__expf(v.x - vmax) + __expf(v.y - vmax) +
                     __expf(v.z - vmax) + __expf(v.w - vmax))
                  : 0.f;
#pragma unroll
    for (int s = 16; s >= 1; s >>= 1) e += __shfl_xor_sync(0xffffffffu, e, s);
    __syncthreads();
    if (lane == 0) sred[wid] = e;
    __syncthreads();
    float e8 = (lane < 8) ? sred[lane] : 0.f;
#pragma unroll
    for (int s = 4; s >= 1; s >>= 1) e8 += __shfl_xor_sync(0xffffffffu, e8, s);
    float denom = vmax + logf(__shfl_sync(0xffffffffu, e8, 0));

    if (act) {
        float4 o;
        o.x = v.x - denom; o.y = v.y - denom;
        o.z = v.z - denom; o.w = v.w - denom;
        *(float4*)&orow[t * 4] = o;
    }
}

// ---------------------------------------------------------------------------
extern "C" void kernel_launch(void* const* d_in, const int* in_sizes, int n_in,
                              void* d_out, int out_size) {
    (void)in_sizes; (void)n_in; (void)out_size;
    const float* x  = (const float*)d_in[0];
    const float* Ww = (const float*)d_in[1];
    const float* Wb = (const float*)d_in[2];
    const float* Lw = (const float*)d_in[3];
    const float* Lb = (const float*)d_in[4];
    float* out = (float*)d_out;

    static bool attr_set = false;
    if (!attr_set) {
        cudaFuncSetAttribute(mma_gemm_k, cudaFuncAttributeMaxDynamicSharedMemorySize, DYN_SMEM);
        attr_set = true;
    }

    __nv_bfloat16 *Xb_hi, *Xb_lo, *Xt_hi, *Xt_lo, *Wwh, *Wwl, *Lwh, *Lwl;
    __nv_bfloat16 *Gh, *Gl, *Mth, *Mtl, *yh, *yl;
    float *sptr, *Lbp, *logits, *Gp, *Mtp;
    cudaGetSymbolAddress((void**)&Xb_hi, g_Xb_hi);
    cudaGetSymbolAddress((void**)&Xb_lo, g_Xb_lo);
    cudaGetSymbolAddress((void**)&Xt_hi, g_Xt_hi);
    cudaGetSymbolAddress((void**)&Xt_lo, g_Xt_lo);
    cudaGetSymbolAddress((void**)&Wwh, g_Ww_hi);
    cudaGetSymbolAddress((void**)&Wwl, g_Ww_lo);
    cudaGetSymbolAddress((void**)&Lwh, g_Lw_hi);
    cudaGetSymbolAddress((void**)&Lwl, g_Lw_lo);
    cudaGetSymbolAddress((void**)&Gh, g_G_hi);
    cudaGetSymbolAddress((void**)&Gl, g_G_lo);
    cudaGetSymbolAddress((void**)&Mth, g_Mt_hi);
    cudaGetSymbolAddress((void**)&Mtl, g_Mt_lo);
    cudaGetSymbolAddress((void**)&yh, g_y_hi);
    cudaGetSymbolAddress((void**)&yl, g_y_lo);
    cudaGetSymbolAddress((void**)&sptr, g_s);
    cudaGetSymbolAddress((void**)&Lbp, g_Lbp);
    cudaGetSymbolAddress((void**)&logits, g_logits);
    cudaGetSymbolAddress((void**)&Gp, g_Gp);
    cudaGetSymbolAddress((void**)&Mtp, g_Mtp);

    prep_x_k<<<dim3(KL / 64, KD / 64, KB), 256>>>(x);
    colsum_final_k<<<(KB * KD) / 256, 256>>>();
    prep_w_k<<<KVP, 256>>>(Ww, Lw, Lb);

    // G[b] = Xt * Xt^T  (512x512, K=4096), K-split x2 -> fp32 partials
    mma_gemm_k<<<dim3(4, 4, KB * 2), 256, DYN_SMEM>>>(
        Xt_hi, Xt_lo, (size_t)KD * KL, Xt_hi, Xt_lo, (size_t)KD * KL,
        KL, KL / 2, 2, nullptr, nullptr, Gp, (size_t)KD * KD, KD, nullptr, 3);
    reduce_split_k<<<2048, 256>>>(Gp, 2, Gh, Gl, nullptr, nullptr, 0);

    // Mt[b] = G * Ww^T  (512x512, K=512), K-split x4; rank-1 s(x)Wb in reduce
    mma_gemm_k<<<dim3(4, 4, KB * 4), 256, DYN_SMEM>>>(
        Gh, Gl, (size_t)KD * KD, Wwh, Wwl, 0,
        KD, KD / 4, 4, nullptr, nullptr, Mtp, (size_t)KD * KD, KD, nullptr, 3);
    reduce_split_k<<<2048, 256>>>(Mtp, 4, Mth, Mtl, sptr, Wb, 1);

    // y[b] = Xb * Mt^T  (4096x512, K=512)
    mma_gemm_k<<<dim3(32, 4, KB), 256, DYN_SMEM>>>(
        Xb_hi, Xb_lo, (size_t)KL * KD, Mth, Mtl, (size_t)KD * KD,
        KD, KD, 1, yh, yl, nullptr, (size_t)KL * KD, KD, nullptr, 0);

    // logits = y * Lw^T + Lb  (16384 x 1024, K=512)
    mma_gemm_k<<<dim3(128, 8, 1), 256, DYN_SMEM>>>(
        yh, yl, 0, Lwh, Lwl, 0,
        KD, KD, 1, nullptr, nullptr, logits, 0, KVP, Lbp, 2);

    logsoftmax_k<<<dim3(KL, KB), 256>>>(out);
}

// round 6
// speedup vs baseline: 3.8323x; 1.2100x over previous
#include <cuda_runtime.h>
#include <cuda_bf16.h>
#include <cstdint>

#define KL 4096
#define KB 4
#define KD 512
#define KV 1000
#define KVP 1024   // padded vocab

// ---------------------------------------------------------------------------
// PTX helpers (sm_80-compatible only: ldmatrix / mma.sync / cp.async)
// ---------------------------------------------------------------------------
__device__ __forceinline__ uint32_t smem_to_u32(const void* p) {
    uint32_t a;
    asm("{ .reg .u64 t; cvta.to.shared.u64 t, %1; cvt.u32.u64 %0, t; }" : "=r"(a) : "l"(p));
    return a;
}
__device__ __forceinline__ void cpasync16(uint32_t s, const void* g) {
    asm volatile("cp.async.cg.shared.global [%0], [%1], 16;" :: "r"(s), "l"(g));
}
__device__ __forceinline__ void cp_commit() {
    asm volatile("cp.async.commit_group;" ::: "memory");
}
template <int N>
__device__ __forceinline__ void cp_wait() {
    asm volatile("cp.async.wait_group %0;" :: "n"(N) : "memory");
}
__device__ __forceinline__ void ldmx4(uint32_t* r, uint32_t a) {
    asm volatile("ldmatrix.sync.aligned.m8n8.x4.shared.b16 {%0,%1,%2,%3}, [%4];"
                 : "=r"(r[0]), "=r"(r[1]), "=r"(r[2]), "=r"(r[3]) : "r"(a));
}
__device__ __forceinline__ void mma16816(float* d, const uint32_t* a, const uint32_t* b) {
    asm volatile(
        "mma.sync.aligned.m16n8k16.row.col.f32.bf16.bf16.f32 "
        "{%0,%1,%2,%3}, {%4,%5,%6,%7}, {%8,%9}, {%0,%1,%2,%3};"
        : "+f"(d[0]), "+f"(d[1]), "+f"(d[2]), "+f"(d[3])
        : "r"(a[0]), "r"(a[1]), "r"(a[2]), "r"(a[3]), "r"(b[0]), "r"(b[1]));
}
#define SMEM_SWIZZLE_128B(o) ((o) ^ (((o) >> 3) & 0x70))

// symmetric-G tile pair tables (upper triangle of 4x4)
__constant__ int c_pi[10] = {0, 0, 0, 0, 1, 1, 1, 2, 2, 3};
__constant__ int c_pj[10] = {0, 1, 2, 3, 1, 2, 3, 2, 3, 3};
__constant__ int c_PT[16] = {0, 1, 2, 3,  0, 4, 5, 6,  0, 0, 7, 8,  0, 0, 0, 9};

// ---------------------------------------------------------------------------
// scratch (static device globals; no allocations)
// ---------------------------------------------------------------------------
#define G_NSPLIT 4
#define M_NSPLIT 2
__device__ __align__(128) float g_part2[KB * KD * 64];   // colsum partials
__device__ __align__(128) float g_s[KB * KD];
__device__ __align__(128) __nv_bfloat16 g_Xb_hi[(size_t)KB * KL * KD], g_Xb_lo[(size_t)KB * KL * KD];
__device__ __align__(128) __nv_bfloat16 g_Xt_hi[(size_t)KB * KD * KL], g_Xt_lo[(size_t)KB * KD * KL];
__device__ __align__(128) __nv_bfloat16 g_Ww_hi[KD * KD], g_Ww_lo[KD * KD];
__device__ __align__(128) __nv_bfloat16 g_Lw_hi[KVP * KD], g_Lw_lo[KVP * KD];
__device__ __align__(128) float g_Lbp[KVP];
__device__ __align__(128) float g_Gp[(size_t)KB * G_NSPLIT * 10 * 128 * 128]; // 10.5 MB
__device__ __align__(128) float g_Mp[(size_t)M_NSPLIT * KB * KD * KD];        // 8 MB
__device__ __align__(128) __nv_bfloat16 g_G_hi[KB * KD * KD], g_G_lo[KB * KD * KD];
__device__ __align__(128) __nv_bfloat16 g_M_hi[KB * KD * KD], g_M_lo[KB * KD * KD];
__device__ __align__(128) __nv_bfloat16 g_P_hi[(size_t)KB * KVP * KD], g_P_lo[(size_t)KB * KVP * KD];
__device__ __align__(128) float g_logits[(size_t)KB * KL * KVP];

__device__ __forceinline__ void split_f32(float v, __nv_bfloat16& h, __nv_bfloat16& l) {
    h = __float2bfloat16(v);
    l = __float2bfloat16(v - __bfloat162float(h));
}

// ---------------------------------------------------------------------------
// prep_x: x (L,B,D) fp32 -> Xb[b][l][d] hi/lo, Xt[b][d][l] hi/lo, colsum partials
// ---------------------------------------------------------------------------
__global__ __launch_bounds__(256) void prep_x_k(const float* __restrict__ x) {
    __shared__ __nv_bfloat16 shi[64][65], slo[64][65];
    __shared__ float ssum[4][64];
    int b = blockIdx.z;
    int lblk = blockIdx.x;
    int l0 = lblk * 64, d0 = blockIdx.y * 64;
    int t = threadIdx.x;
    int c = t & 63, r4 = t >> 6;
    float ps = 0.f;
#pragma unroll 4
    for (int rr = 0; rr < 16; rr++) {
        int r = r4 * 16 + rr;
        float v = x[(size_t)(l0 + r) * (KB * KD) + b * KD + d0 + c];
        ps += v;
        __nv_bfloat16 h, l;
        split_f32(v, h, l);
        size_t o = ((size_t)b * KL + (l0 + r)) * KD + d0 + c;
        g_Xb_hi[o] = h; g_Xb_lo[o] = l;
        shi[r][c] = h; slo[r][c] = l;
    }
    ssum[r4][c] = ps;
    __syncthreads();
#pragma unroll 4
    for (int rr = 0; rr < 16; rr++) {
        int r = r4 * 16 + rr;   // d index
        size_t o = ((size_t)b * KD + (d0 + r)) * KL + l0 + c;
        g_Xt_hi[o] = shi[c][r];
        g_Xt_lo[o] = slo[c][r];
    }
    if (t < 64) {
        float s = ssum[0][t] + ssum[1][t] + ssum[2][t] + ssum[3][t];
        g_part2[((size_t)b * KD + d0 + t) * 64 + lblk] = s;
    }
}

__global__ void colsum_final_k() {
    int idx = blockIdx.x * 256 + threadIdx.x;  // KB*KD
    float s = 0.f;
    const float* p = &g_part2[(size_t)idx * 64];
#pragma unroll
    for (int k = 0; k < 64; k++) s += p[k];
    g_s[idx] = s;
}

// ---------------------------------------------------------------------------
// prep_w (flat): split Ww; split Lw padded to 1024 rows; pad Lb
// ---------------------------------------------------------------------------
__global__ void prep_w_k(const float* __restrict__ Ww, const float* __restrict__ Lw,
                         const float* __restrict__ Lb) {
    int idx = blockIdx.x * 256 + threadIdx.x;   // over KVP*KD
    int row = idx / KD;
    float v2 = (row < KV) ? Lw[idx] : 0.f;
    __nv_bfloat16 h2, l2;
    split_f32(v2, h2, l2);
    g_Lw_hi[idx] = h2; g_Lw_lo[idx] = l2;
    if (idx < KD * KD) {
        __nv_bfloat16 h, l;
        split_f32(Ww[idx], h, l);
        g_Ww_hi[idx] = h; g_Ww_lo[idx] = l;
    }
    if (idx < KVP) g_Lbp[idx] = (idx < KV) ? Lb[idx] : 0.f;
}

// ---------------------------------------------------------------------------
// mma.sync bf16 split GEMM: C[m][n] = sum_k A[m][k]*B[n][k], hi/lo 3-product
//   mode 0: write Chi/Clo bf16 (batch b)
//   mode 2: write Cf fp32 + bias[col] (batch b)
//   mode 3: write Cf fp32 K-split partial (slot blockIdx.z)
//   mode 4: symmetric pairs — i0/j0 from c_pi/c_pj[blockIdx.x]; write local
//           128x128 fp32 tile at slot (blockIdx.z*gridDim.x + blockIdx.x)
// CTA tile 128x128, K-chunk 64, 3-stage cp.async, one barrier per chunk.
// ---------------------------------------------------------------------------
#define TILE_BYTES 16384               // 128 rows x 128B (64 bf16)
#define STAGE_BYTES (4 * TILE_BYTES)   // Ah, Al, Bh, Bl
#define NSTAGE 3
#define DYN_SMEM (NSTAGE * STAGE_BYTES)  // 192 KB

__global__ __launch_bounds__(256, 1) void mma_gemm_k(
    const __nv_bfloat16* __restrict__ Ahi, const __nv_bfloat16* __restrict__ Alo, size_t sA,
    const __nv_bfloat16* __restrict__ Bhi, const __nv_bfloat16* __restrict__ Blo, size_t sB,
    int ldk, int Kiter, int nsplit,
    __nv_bfloat16* __restrict__ Chi, __nv_bfloat16* __restrict__ Clo,
    float* __restrict__ Cf, size_t sC, int ldc,
    const float* __restrict__ bias, int mode) {
    extern __shared__ __align__(1024) char smem[];
    uint32_t smb = smem_to_u32(smem);
    int tid = threadIdx.x;
    int wid = tid >> 5, lane = tid & 31;
    int b = blockIdx.z / nsplit, sp = blockIdx.z % nsplit;
    int koff0 = sp * Kiter;
    int i0, j0;
    if (mode == 4) {
        i0 = c_pi[blockIdx.x] * 128;
        j0 = c_pj[blockIdx.x] * 128;
    } else {
        i0 = blockIdx.x * 128;
        j0 = blockIdx.y * 128;
    }
    int wm = (wid >> 2) * 64, wn = (wid & 3) * 32;

    const __nv_bfloat16* tiles[4] = {Ahi + sA * b, Alo + sA * b, Bhi + sB * b, Blo + sB * b};
    const int row0[4] = {i0, i0, j0, j0};
    const int NC = Kiter >> 6;

    int lr[4], lu[4];
#pragma unroll
    for (int it = 0; it < 4; it++) {
        int q = tid + it * 256;
        lr[it] = q >> 3;
        lu[it] = q & 7;
    }

    auto load_chunk = [&](int chunk) {
        uint32_t sbase = smb + (chunk % NSTAGE) * STAGE_BYTES;
        int koff = koff0 + (chunk << 6);
#pragma unroll
        for (int tile = 0; tile < 4; tile++) {
            const __nv_bfloat16* src = tiles[tile];
#pragma unroll
            for (int it = 0; it < 4; it++) {
                uint32_t boff = (uint32_t)(lr[it] * 128 + lu[it] * 16);
                uint32_t sw = SMEM_SWIZZLE_128B(boff);
                const void* g = src + (size_t)(row0[tile] + lr[it]) * ldk + koff + lu[it] * 8;
                cpasync16(sbase + tile * TILE_BYTES + sw, g);
            }
        }
        cp_commit();
    };

    float acc[4][4][4];
#pragma unroll
    for (int a = 0; a < 4; a++)
#pragma unroll
        for (int bb = 0; bb < 4; bb++)
#pragma unroll
            for (int c = 0; c < 4; c++) acc[a][bb][c] = 0.f;

    int arow = wm + (lane & 15);
    int akh16 = ((lane >> 4) & 1) * 16;
    int brow = wn + ((lane >> 4) & 1) * 8 + (lane & 7);
    int bkh16 = ((lane >> 3) & 1) * 16;

    load_chunk(0);
    if (NC > 1) load_chunk(1);

    for (int kc = 0; kc < NC; kc++) {
        if (kc < NC - 1) cp_wait<1>();
        else cp_wait<0>();
        __syncthreads();

        uint32_t sAh = smb + (kc % NSTAGE) * STAGE_BYTES;
        uint32_t sAl = sAh + TILE_BYTES;
        uint32_t sBh = sAh + 2 * TILE_BYTES;
        uint32_t sBl = sAh + 3 * TILE_BYTES;

#pragma unroll
        for (int kk = 0; kk < 4; kk++) {
            uint32_t ah[4][4], al[4][4], bh[2][4], bl[2][4];
#pragma unroll
            for (int mt = 0; mt < 4; mt++) {
                uint32_t o = (uint32_t)((arow + mt * 16) * 128 + kk * 32 + akh16);
                uint32_t sw = SMEM_SWIZZLE_128B(o);
                ldmx4(ah[mt], sAh + sw);
                ldmx4(al[mt], sAl + sw);
            }
#pragma unroll
            for (int np = 0; np < 2; np++) {
                uint32_t o = (uint32_t)((brow + np * 16) * 128 + kk * 32 + bkh16);
                uint32_t sw = SMEM_SWIZZLE_128B(o);
                ldmx4(bh[np], sBh + sw);
                ldmx4(bl[np], sBl + sw);
            }
#pragma unroll
            for (int mt = 0; mt < 4; mt++)
#pragma unroll
                for (int nt = 0; nt < 4; nt++) {
                    uint32_t* bfh = &bh[nt >> 1][(nt & 1) * 2];
                    uint32_t* bfl = &bl[nt >> 1][(nt & 1) * 2];
                    mma16816(acc[mt][nt], ah[mt], bfh);  // hi*hi
                    mma16816(acc[mt][nt], ah[mt], bfl);  // hi*lo
                    mma16816(acc[mt][nt], al[mt], bfh);  // lo*hi
                }
        }
        // issue next load AFTER compute: barrier at top of this iter already
        // guaranteed all warps are done with the stage this overwrites.
        if (kc + 2 < NC) load_chunk(kc + 2);
    }

    // ---- epilogue ----
    float* loc = (mode == 4)
        ? Cf + ((size_t)blockIdx.z * gridDim.x + blockIdx.x) * (128 * 128)
        : nullptr;
#pragma unroll
    for (int mt = 0; mt < 4; mt++) {
#pragma unroll
        for (int half = 0; half < 2; half++) {
            int lrow = wm + mt * 16 + (lane >> 2) + half * 8;
            int grow = i0 + lrow;
#pragma unroll
            for (int nt = 0; nt < 4; nt++) {
                int lcol = wn + nt * 8 + (lane & 3) * 2;
                int gcol = j0 + lcol;
                float v0 = acc[mt][nt][half * 2 + 0];
                float v1 = acc[mt][nt][half * 2 + 1];
                if (mode == 4) {
                    *(float2*)&loc[lrow * 128 + lcol] = make_float2(v0, v1);
                } else if (mode == 3) {
                    *(float2*)&Cf[sC * blockIdx.z + (size_t)grow * ldc + gcol] = make_float2(v0, v1);
                } else if (mode == 2) {
                    float2 f2 = make_float2(v0 + bias[gcol], v1 + bias[gcol + 1]);
                    *(float2*)&Cf[sC * b + (size_t)grow * ldc + gcol] = f2;
                } else {
                    __nv_bfloat162 h2, l2;
                    split_f32(v0, h2.x, l2.x);
                    split_f32(v1, h2.y, l2.y);
                    *(__nv_bfloat162*)&Chi[sC * b + (size_t)grow * ldc + gcol] = h2;
                    *(__nv_bfloat162*)&Clo[sC * b + (size_t)grow * ldc + gcol] = l2;
                }
            }
        }
    }
}

// ---------------------------------------------------------------------------
// reduce symmetric-G partials (10 tile-pairs x G_NSPLIT) -> full G hi/lo bf16
// ---------------------------------------------------------------------------
__global__ void reduce_G_k() {
    size_t idx = ((size_t)blockIdx.x * 256 + threadIdx.x) * 2;  // KB*KD*KD elems
    const size_t per = (size_t)KD * KD;
    int b = (int)(idx / per);
    size_t rem = idx % per;
    int i = (int)(rem / KD), j = (int)(rem % KD);
    int ti = i >> 7, tj = j >> 7;
    float s0 = 0.f, s1 = 0.f;
    if (ti <= tj) {
        int p = c_PT[ti * 4 + tj];
        size_t off = (size_t)((i & 127) * 128 + (j & 127));
        for (int sp = 0; sp < G_NSPLIT; sp++) {
            const float* base = g_Gp + ((size_t)(b * G_NSPLIT + sp) * 10 + p) * (128 * 128);
            s0 += base[off];
            s1 += base[off + 1];
        }
    } else {
        int p = c_PT[tj * 4 + ti];
        size_t off = (size_t)((j & 127) * 128 + (i & 127));
        for (int sp = 0; sp < G_NSPLIT; sp++) {
            const float* base = g_Gp + ((size_t)(b * G_NSPLIT + sp) * 10 + p) * (128 * 128);
            s0 += base[off];
            s1 += base[off + 128];   // G[i][j+1] = mirrored tile, next row
        }
    }
    __nv_bfloat162 h2, l2;
    split_f32(s0, h2.x, l2.x);
    split_f32(s1, h2.y, l2.y);
    *(__nv_bfloat162*)&g_G_hi[idx] = h2;
    *(__nv_bfloat162*)&g_G_lo[idx] = l2;
}

// ---------------------------------------------------------------------------
// reduce M K-split partials + rank-1 Wb[i]*s[b][j] -> hi/lo bf16
//   M[b][i][j] = sum_k Ww[i][k] G[b][j][k]  (G sym)  + Wb[i]*s[b][j]
// ---------------------------------------------------------------------------
__global__ void reduce_M_k(const float* __restrict__ Wb) {
    size_t idx = ((size_t)blockIdx.x * 256 + threadIdx.x) * 2;
    const size_t per = (size_t)KD * KD;
    int b = (int)(idx / per);
    size_t rem = idx % per;
    int i = (int)(rem / KD), j = (int)(rem % KD);
    float s0 = 0.f, s1 = 0.f;
    for (int sp = 0; sp < M_NSPLIT; sp++) {
        const float* p = g_Mp + ((size_t)(b * M_NSPLIT + sp)) * per + rem;
        s0 += p[0];
        s1 += p[1];
    }
    float u = Wb[i];
    s0 += u * g_s[b * KD + j];
    s1 += u * g_s[b * KD + j + 1];
    __nv_bfloat162 h2, l2;
    split_f32(s0, h2.x, l2.x);
    split_f32(s1, h2.y, l2.y);
    *(__nv_bfloat162*)&g_M_hi[idx] = h2;
    *(__nv_bfloat162*)&g_M_lo[idx] = l2;
}

// ---------------------------------------------------------------------------
// log_softmax over V + permute (B,L,V)->(L,B,V)
// ---------------------------------------------------------------------------
__global__ void logsoftmax_k(float* __restrict__ out) {
    int l = blockIdx.x, b = blockIdx.y;
    const float* row = g_logits + (size_t)(b * KL + l) * KVP;
    float* orow = out + (size_t)(l * KB + b) * KV;
    __shared__ float sred[8];
    int t = threadIdx.x;
    int wid = t >> 5, lane = t & 31;
    bool act = t < (KV / 4);
    float4 v = act ? *(const float4*)&row[t * 4]
                   : make_float4(-3.4e38f, -3.4e38f, -3.4e38f, -3.4e38f);
    float m = fmaxf(fmaxf(v.x, v.y), fmaxf(v.z, v.w));
#pragma unroll
    for (int s = 16; s >= 1; s >>= 1) m = fmaxf(m, __shfl_xor_sync(0xffffffffu, m, s));
    if (lane == 0) sred[wid] = m;
    __syncthreads();
    float m8 = (lane < 8) ? sred[lane] : -3.4e38f;
#pragma unroll
    for (int s = 4; s >= 1; s >>= 1) m8 = fmaxf(m8, __shfl_xor_sync(0xffffffffu, m8, s));
    float vmax = __shfl_sync(0xffffffffu, m8, 0);

    float e = act ? (__expf(v.x - vmax) + __expf(v.y - vmax) +
                     __expf(v.z - vmax) + __expf(v.w - vmax))
                  : 0.f;
#pragma unroll
    for (int s = 16; s >= 1; s >>= 1) e += __shfl_xor_sync(0xffffffffu, e, s);
    __syncthreads();
    if (lane == 0) sred[wid] = e;
    __syncthreads();
    float e8 = (lane < 8) ? sred[lane] : 0.f;
#pragma unroll
    for (int s = 4; s >= 1; s >>= 1) e8 += __shfl_xor_sync(0xffffffffu, e8, s);
    float denom = vmax + logf(__shfl_sync(0xffffffffu, e8, 0));

    if (act) {
        float4 o;
        o.x = v.x - denom; o.y = v.y - denom;
        o.z = v.z - denom; o.w = v.w - denom;
        *(float4*)&orow[t * 4] = o;
    }
}

// ---------------------------------------------------------------------------
extern "C" void kernel_launch(void* const* d_in, const int* in_sizes, int n_in,
                              void* d_out, int out_size) {
    (void)in_sizes; (void)n_in; (void)out_size;
    const float* x  = (const float*)d_in[0];
    const float* Ww = (const float*)d_in[1];
    const float* Wb = (const float*)d_in[2];
    const float* Lw = (const float*)d_in[3];
    const float* Lb = (const float*)d_in[4];
    float* out = (float*)d_out;

    static bool attr_set = false;
    if (!attr_set) {
        cudaFuncSetAttribute(mma_gemm_k, cudaFuncAttributeMaxDynamicSharedMemorySize, DYN_SMEM);
        attr_set = true;
    }

    __nv_bfloat16 *Xb_hi, *Xb_lo, *Xt_hi, *Xt_lo, *Wwh, *Wwl, *Lwh, *Lwl;
    __nv_bfloat16 *Gh, *Gl, *Mh, *Ml, *Ph, *Pl;
    float *Lbp, *logits, *Gp, *Mp;
    cudaGetSymbolAddress((void**)&Xb_hi, g_Xb_hi);
    cudaGetSymbolAddress((void**)&Xb_lo, g_Xb_lo);
    cudaGetSymbolAddress((void**)&Xt_hi, g_Xt_hi);
    cudaGetSymbolAddress((void**)&Xt_lo, g_Xt_lo);
    cudaGetSymbolAddress((void**)&Wwh, g_Ww_hi);
    cudaGetSymbolAddress((void**)&Wwl, g_Ww_lo);
    cudaGetSymbolAddress((void**)&Lwh, g_Lw_hi);
    cudaGetSymbolAddress((void**)&Lwl, g_Lw_lo);
    cudaGetSymbolAddress((void**)&Gh, g_G_hi);
    cudaGetSymbolAddress((void**)&Gl, g_G_lo);
    cudaGetSymbolAddress((void**)&Mh, g_M_hi);
    cudaGetSymbolAddress((void**)&Ml, g_M_lo);
    cudaGetSymbolAddress((void**)&Ph, g_P_hi);
    cudaGetSymbolAddress((void**)&Pl, g_P_lo);
    cudaGetSymbolAddress((void**)&Lbp, g_Lbp);
    cudaGetSymbolAddress((void**)&logits, g_logits);
    cudaGetSymbolAddress((void**)&Gp, g_Gp);
    cudaGetSymbolAddress((void**)&Mp, g_Mp);

    prep_x_k<<<dim3(KL / 64, KD / 64, KB), 256>>>(x);
    colsum_final_k<<<(KB * KD) / 256, 256>>>();
    prep_w_k<<<(KVP * KD) / 256, 256>>>(Ww, Lw, Lb);

    // G[b] = Xt*Xt^T (symmetric): 10 upper tile-pairs, K-split x4 -> partials
    mma_gemm_k<<<dim3(10, 1, KB * G_NSPLIT), 256, DYN_SMEM>>>(
        Xt_hi, Xt_lo, (size_t)KD * KL, Xt_hi, Xt_lo, (size_t)KD * KL,
        KL, KL / G_NSPLIT, G_NSPLIT, nullptr, nullptr, Gp, 0, 128, nullptr, 4);
    reduce_G_k<<<(KB * KD * KD / 2) / 256, 256>>>();

    // M[b] = Ww*G[b]^T (512x512, K=512): A=Ww (unbatched), B=G (batched);
    // K-split x2; rank-1 Wb (x) s added in reduce
    mma_gemm_k<<<dim3(4, 4, KB * M_NSPLIT), 256, DYN_SMEM>>>(
        Wwh, Wwl, 0, Gh, Gl, (size_t)KD * KD,
        KD, KD / M_NSPLIT, M_NSPLIT, nullptr, nullptr, Mp, (size_t)KD * KD, KD, nullptr, 3);
    reduce_M_k<<<(KB * KD * KD / 2) / 256, 256>>>(Wb);

    // P[b][v][k] = sum_n Lw[v][n] * M[b][k][n]  (A=Lw, B=M) -> bf16 split
    mma_gemm_k<<<dim3(KVP / 128, KD / 128, KB), 256, DYN_SMEM>>>(
        Lwh, Lwl, 0, Mh, Ml, (size_t)KD * KD,
        KD, KD, 1, Ph, Pl, nullptr, (size_t)KVP * KD, KD, nullptr, 0);

    // logits[b] = Xb * P^T + Lb  (4096x1024, K=512)
    mma_gemm_k<<<dim3(KL / 128, KVP / 128, KB), 256, DYN_SMEM>>>(
        Xb_hi, Xb_lo, (size_t)KL * KD, Ph, Pl, (size_t)KVP * KD,
        KD, KD, 1, nullptr, nullptr, logits, (size_t)KL * KVP, KVP, Lbp, 2);

    logsoftmax_k<<<dim3(KL, KB), 256>>>(out);
}

// round 7
// speedup vs baseline: 4.1271x; 1.0769x over previous
#include <cuda_runtime.h>
#include <cuda_bf16.h>
#include <cstdint>

#define KL 4096
#define KB 4
#define KD 512
#define KV 1000
#define KVP 1024   // padded vocab

// ---------------------------------------------------------------------------
// PTX helpers (sm_80-compatible only: ldmatrix / mma.sync / cp.async)
// ---------------------------------------------------------------------------
__device__ __forceinline__ uint32_t smem_to_u32(const void* p) {
    uint32_t a;
    asm("{ .reg .u64 t; cvta.to.shared.u64 t, %1; cvt.u32.u64 %0, t; }" : "=r"(a) : "l"(p));
    return a;
}
__device__ __forceinline__ void cpasync16(uint32_t s, const void* g) {
    asm volatile("cp.async.cg.shared.global [%0], [%1], 16;" :: "r"(s), "l"(g));
}
__device__ __forceinline__ void cp_commit() {
    asm volatile("cp.async.commit_group;" ::: "memory");
}
template <int N>
__device__ __forceinline__ void cp_wait() {
    asm volatile("cp.async.wait_group %0;" :: "n"(N) : "memory");
}
__device__ __forceinline__ void ldmx4(uint32_t* r, uint32_t a) {
    asm volatile("ldmatrix.sync.aligned.m8n8.x4.shared.b16 {%0,%1,%2,%3}, [%4];"
                 : "=r"(r[0]), "=r"(r[1]), "=r"(r[2]), "=r"(r[3]) : "r"(a));
}
__device__ __forceinline__ void mma16816(float* d, const uint32_t* a, const uint32_t* b) {
    asm volatile(
        "mma.sync.aligned.m16n8k16.row.col.f32.bf16.bf16.f32 "
        "{%0,%1,%2,%3}, {%4,%5,%6,%7}, {%8,%9}, {%0,%1,%2,%3};"
        : "+f"(d[0]), "+f"(d[1]), "+f"(d[2]), "+f"(d[3])
        : "r"(a[0]), "r"(a[1]), "r"(a[2]), "r"(a[3]), "r"(b[0]), "r"(b[1]));
}
#define SMEM_SWIZZLE_128B(o) ((o) ^ (((o) >> 3) & 0x70))

// symmetric-G tile pair tables (upper triangle of 4x4)
__constant__ int c_pi[10] = {0, 0, 0, 0, 1, 1, 1, 2, 2, 3};
__constant__ int c_pj[10] = {0, 1, 2, 3, 1, 2, 3, 2, 3, 3};
__constant__ int c_PT[16] = {0, 1, 2, 3,  0, 4, 5, 6,  0, 0, 7, 8,  0, 0, 0, 9};

// ---------------------------------------------------------------------------
// scratch (static device globals; no allocations)
// ---------------------------------------------------------------------------
#define G_NSPLIT 3   // 10 pairs * KB * 3 = 120 CTAs -> single wave on 148 SMs
#define M_NSPLIT 2
__device__ __align__(128) float g_part2[KB * KD * 64];   // colsum partials
__device__ __align__(128) float g_s[KB * KD];
__device__ __align__(128) __nv_bfloat16 g_Xb_hi[(size_t)KB * KL * KD], g_Xb_lo[(size_t)KB * KL * KD];
__device__ __align__(128) __nv_bfloat16 g_Xt_hi[(size_t)KB * KD * KL], g_Xt_lo[(size_t)KB * KD * KL];
__device__ __align__(128) __nv_bfloat16 g_Ww_hi[KD * KD], g_Ww_lo[KD * KD];
__device__ __align__(128) __nv_bfloat16 g_Lw_hi[KVP * KD], g_Lw_lo[KVP * KD];
__device__ __align__(128) float g_Lbp[KVP];
__device__ __align__(128) float g_Gp[(size_t)KB * G_NSPLIT * 10 * 128 * 128]; // 7.9 MB
__device__ __align__(128) float g_Mp[(size_t)M_NSPLIT * KB * KD * KD];        // 8 MB
__device__ __align__(128) __nv_bfloat16 g_G_hi[KB * KD * KD], g_G_lo[KB * KD * KD];
__device__ __align__(128) __nv_bfloat16 g_M_hi[KB * KD * KD], g_M_lo[KB * KD * KD];
__device__ __align__(128) __nv_bfloat16 g_P_hi[(size_t)KB * KVP * KD], g_P_lo[(size_t)KB * KVP * KD];
__device__ __align__(128) float g_logits[(size_t)KB * KL * KVP];

__device__ __forceinline__ void split_f32(float v, __nv_bfloat16& h, __nv_bfloat16& l) {
    h = __float2bfloat16(v);
    l = __float2bfloat16(v - __bfloat162float(h));
}

// ---------------------------------------------------------------------------
// prep_x: x (L,B,D) fp32 -> Xb[b][l][d] hi/lo, Xt[b][d][l] hi/lo, colsum partials
// ---------------------------------------------------------------------------
__global__ __launch_bounds__(256) void prep_x_k(const float* __restrict__ x) {
    __shared__ __nv_bfloat16 shi[64][65], slo[64][65];
    __shared__ float ssum[4][64];
    int b = blockIdx.z;
    int lblk = blockIdx.x;
    int l0 = lblk * 64, d0 = blockIdx.y * 64;
    int t = threadIdx.x;
    int c = t & 63, r4 = t >> 6;
    float ps = 0.f;
#pragma unroll 4
    for (int rr = 0; rr < 16; rr++) {
        int r = r4 * 16 + rr;
        float v = x[(size_t)(l0 + r) * (KB * KD) + b * KD + d0 + c];
        ps += v;
        __nv_bfloat16 h, l;
        split_f32(v, h, l);
        size_t o = ((size_t)b * KL + (l0 + r)) * KD + d0 + c;
        g_Xb_hi[o] = h; g_Xb_lo[o] = l;
        shi[r][c] = h; slo[r][c] = l;
    }
    ssum[r4][c] = ps;
    __syncthreads();
#pragma unroll 4
    for (int rr = 0; rr < 16; rr++) {
        int r = r4 * 16 + rr;   // d index
        size_t o = ((size_t)b * KD + (d0 + r)) * KL + l0 + c;
        g_Xt_hi[o] = shi[c][r];
        g_Xt_lo[o] = slo[c][r];
    }
    if (t < 64) {
        float s = ssum[0][t] + ssum[1][t] + ssum[2][t] + ssum[3][t];
        g_part2[((size_t)b * KD + d0 + t) * 64 + lblk] = s;
    }
}

__global__ void colsum_final_k() {
    int idx = blockIdx.x * 256 + threadIdx.x;  // KB*KD
    float s = 0.f;
    const float* p = &g_part2[(size_t)idx * 64];
#pragma unroll
    for (int k = 0; k < 64; k++) s += p[k];
    g_s[idx] = s;
}

// ---------------------------------------------------------------------------
// prep_w (flat): split Ww; split Lw padded to 1024 rows; pad Lb
// ---------------------------------------------------------------------------
__global__ void prep_w_k(const float* __restrict__ Ww, const float* __restrict__ Lw,
                         const float* __restrict__ Lb) {
    int idx = blockIdx.x * 256 + threadIdx.x;   // over KVP*KD
    int row = idx / KD;
    float v2 = (row < KV) ? Lw[idx] : 0.f;
    __nv_bfloat16 h2, l2;
    split_f32(v2, h2, l2);
    g_Lw_hi[idx] = h2; g_Lw_lo[idx] = l2;
    if (idx < KD * KD) {
        __nv_bfloat16 h, l;
        split_f32(Ww[idx], h, l);
        g_Ww_hi[idx] = h; g_Ww_lo[idx] = l;
    }
    if (idx < KVP) g_Lbp[idx] = (idx < KV) ? Lb[idx] : 0.f;
}

// ---------------------------------------------------------------------------
// mma.sync bf16 split GEMM: C[m][n] = sum_k A[m][k]*B[n][k], hi/lo 3-product
//   K handled in 64-wide chunks. NCtot total chunks split over nsplit slots;
//   slot sp gets NC = NCtot/nsplit (+1 for sp < NCtot%nsplit), contiguous.
//   mode 0: write Chi/Clo bf16 (batch b)
//   mode 2: write Cf fp32 + bias[col] (batch b)
//   mode 3: write Cf fp32 K-split partial (slot blockIdx.z)
//   mode 4: symmetric pairs — i0/j0 from c_pi/c_pj[blockIdx.x]; write local
//           128x128 fp32 tile at slot (blockIdx.z*gridDim.x + blockIdx.x)
// CTA tile 128x128, K-chunk 64, 3-stage cp.async, one barrier per chunk.
// ---------------------------------------------------------------------------
#define TILE_BYTES 16384               // 128 rows x 128B (64 bf16)
#define STAGE_BYTES (4 * TILE_BYTES)   // Ah, Al, Bh, Bl
#define NSTAGE 3
#define DYN_SMEM (NSTAGE * STAGE_BYTES)  // 192 KB

__global__ __launch_bounds__(256, 1) void mma_gemm_k(
    const __nv_bfloat16* __restrict__ Ahi, const __nv_bfloat16* __restrict__ Alo, size_t sA,
    const __nv_bfloat16* __restrict__ Bhi, const __nv_bfloat16* __restrict__ Blo, size_t sB,
    int ldk, int NCtot, int nsplit,
    __nv_bfloat16* __restrict__ Chi, __nv_bfloat16* __restrict__ Clo,
    float* __restrict__ Cf, size_t sC, int ldc,
    const float* __restrict__ bias, int mode) {
    extern __shared__ __align__(1024) char smem[];
    uint32_t smb = smem_to_u32(smem);
    int tid = threadIdx.x;
    int wid = tid >> 5, lane = tid & 31;
    int b = blockIdx.z / nsplit, sp = blockIdx.z % nsplit;
    // uneven chunk split
    int basec = NCtot / nsplit, remc = NCtot % nsplit;
    int NC = basec + (sp < remc ? 1 : 0);
    int startc = sp * basec + (sp < remc ? sp : remc);
    int koff0 = startc << 6;
    int i0, j0;
    if (mode == 4) {
        i0 = c_pi[blockIdx.x] * 128;
        j0 = c_pj[blockIdx.x] * 128;
    } else {
        i0 = blockIdx.x * 128;
        j0 = blockIdx.y * 128;
    }
    int wm = (wid >> 2) * 64, wn = (wid & 3) * 32;

    const __nv_bfloat16* tiles[4] = {Ahi + sA * b, Alo + sA * b, Bhi + sB * b, Blo + sB * b};
    const int row0[4] = {i0, i0, j0, j0};

    int lr[4], lu[4];
#pragma unroll
    for (int it = 0; it < 4; it++) {
        int q = tid + it * 256;
        lr[it] = q >> 3;
        lu[it] = q & 7;
    }

    auto load_chunk = [&](int chunk) {
        uint32_t sbase = smb + (chunk % NSTAGE) * STAGE_BYTES;
        int koff = koff0 + (chunk << 6);
#pragma unroll
        for (int tile = 0; tile < 4; tile++) {
            const __nv_bfloat16* src = tiles[tile];
#pragma unroll
            for (int it = 0; it < 4; it++) {
                uint32_t boff = (uint32_t)(lr[it] * 128 + lu[it] * 16);
                uint32_t sw = SMEM_SWIZZLE_128B(boff);
                const void* g = src + (size_t)(row0[tile] + lr[it]) * ldk + koff + lu[it] * 8;
                cpasync16(sbase + tile * TILE_BYTES + sw, g);
            }
        }
        cp_commit();
    };

    float acc[4][4][4];
#pragma unroll
    for (int a = 0; a < 4; a++)
#pragma unroll
        for (int bb = 0; bb < 4; bb++)
#pragma unroll
            for (int c = 0; c < 4; c++) acc[a][bb][c] = 0.f;

    int arow = wm + (lane & 15);
    int akh16 = ((lane >> 4) & 1) * 16;
    int brow = wn + ((lane >> 4) & 1) * 8 + (lane & 7);
    int bkh16 = ((lane >> 3) & 1) * 16;

    load_chunk(0);
    if (NC > 1) load_chunk(1);

    for (int kc = 0; kc < NC; kc++) {
        if (kc < NC - 1) cp_wait<1>();
        else cp_wait<0>();
        __syncthreads();

        uint32_t sAh = smb + (kc % NSTAGE) * STAGE_BYTES;
        uint32_t sAl = sAh + TILE_BYTES;
        uint32_t sBh = sAh + 2 * TILE_BYTES;
        uint32_t sBl = sAh + 3 * TILE_BYTES;

#pragma unroll
        for (int kk = 0; kk < 4; kk++) {
            uint32_t ah[4][4], al[4][4], bh[2][4], bl[2][4];
#pragma unroll
            for (int mt = 0; mt < 4; mt++) {
                uint32_t o = (uint32_t)((arow + mt * 16) * 128 + kk * 32 + akh16);
                uint32_t sw = SMEM_SWIZZLE_128B(o);
                ldmx4(ah[mt], sAh + sw);
                ldmx4(al[mt], sAl + sw);
            }
#pragma unroll
            for (int np = 0; np < 2; np++) {
                uint32_t o = (uint32_t)((brow + np * 16) * 128 + kk * 32 + bkh16);
                uint32_t sw = SMEM_SWIZZLE_128B(o);
                ldmx4(bh[np], sBh + sw);
                ldmx4(bl[np], sBl + sw);
            }
#pragma unroll
            for (int mt = 0; mt < 4; mt++)
#pragma unroll
                for (int nt = 0; nt < 4; nt++) {
                    uint32_t* bfh = &bh[nt >> 1][(nt & 1) * 2];
                    uint32_t* bfl = &bl[nt >> 1][(nt & 1) * 2];
                    mma16816(acc[mt][nt], ah[mt], bfh);  // hi*hi
                    mma16816(acc[mt][nt], ah[mt], bfl);  // hi*lo
                    mma16816(acc[mt][nt], al[mt], bfh);  // lo*hi
                }
        }
        // issue next load AFTER compute: barrier at top of this iter already
        // guaranteed all warps are done with the stage this overwrites.
        if (kc + 2 < NC) load_chunk(kc + 2);
    }

    // ---- epilogue ----
    float* loc = (mode == 4)
        ? Cf + ((size_t)blockIdx.z * gridDim.x + blockIdx.x) * (128 * 128)
        : nullptr;
#pragma unroll
    for (int mt = 0; mt < 4; mt++) {
#pragma unroll
        for (int half = 0; half < 2; half++) {
            int lrow = wm + mt * 16 + (lane >> 2) + half * 8;
            int grow = i0 + lrow;
#pragma unroll
            for (int nt = 0; nt < 4; nt++) {
                int lcol = wn + nt * 8 + (lane & 3) * 2;
                int gcol = j0 + lcol;
                float v0 = acc[mt][nt][half * 2 + 0];
                float v1 = acc[mt][nt][half * 2 + 1];
                if (mode == 4) {
                    *(float2*)&loc[lrow * 128 + lcol] = make_float2(v0, v1);
                } else if (mode == 3) {
                    *(float2*)&Cf[sC * blockIdx.z + (size_t)grow * ldc + gcol] = make_float2(v0, v1);
                } else if (mode == 2) {
                    float2 f2 = make_float2(v0 + bias[gcol], v1 + bias[gcol + 1]);
                    *(float2*)&Cf[sC * b + (size_t)grow * ldc + gcol] = f2;
                } else {
                    __nv_bfloat162 h2, l2;
                    split_f32(v0, h2.x, l2.x);
                    split_f32(v1, h2.y, l2.y);
                    *(__nv_bfloat162*)&Chi[sC * b + (size_t)grow * ldc + gcol] = h2;
                    *(__nv_bfloat162*)&Clo[sC * b + (size_t)grow * ldc + gcol] = l2;
                }
            }
        }
    }
}

// ---------------------------------------------------------------------------
// reduce symmetric-G partials (10 tile-pairs x G_NSPLIT) -> full G hi/lo bf16
// ---------------------------------------------------------------------------
__global__ void reduce_G_k() {
    size_t idx = ((size_t)blockIdx.x * 256 + threadIdx.x) * 2;  // KB*KD*KD elems
    const size_t per = (size_t)KD * KD;
    int b = (int)(idx / per);
    size_t rem = idx % per;
    int i = (int)(rem / KD), j = (int)(rem % KD);
    int ti = i >> 7, tj = j >> 7;
    float s0 = 0.f, s1 = 0.f;
    if (ti <= tj) {
        int p = c_PT[ti * 4 + tj];
        size_t off = (size_t)((i & 127) * 128 + (j & 127));
        for (int sp = 0; sp < G_NSPLIT; sp++) {
            const float* base = g_Gp + ((size_t)(b * G_NSPLIT + sp) * 10 + p) * (128 * 128);
            s0 += base[off];
            s1 += base[off + 1];
        }
    } else {
        int p = c_PT[tj * 4 + ti];
        size_t off = (size_t)((j & 127) * 128 + (i & 127));
        for (int sp = 0; sp < G_NSPLIT; sp++) {
            const float* base = g_Gp + ((size_t)(b * G_NSPLIT + sp) * 10 + p) * (128 * 128);
            s0 += base[off];
            s1 += base[off + 128];   // G[i][j+1] = mirrored tile, next row
        }
    }
    __nv_bfloat162 h2, l2;
    split_f32(s0, h2.x, l2.x);
    split_f32(s1, h2.y, l2.y);
    *(__nv_bfloat162*)&g_G_hi[idx] = h2;
    *(__nv_bfloat162*)&g_G_lo[idx] = l2;
}

// ---------------------------------------------------------------------------
// reduce M K-split partials + rank-1 Wb[i]*s[b][j] -> hi/lo bf16
// ---------------------------------------------------------------------------
__global__ void reduce_M_k(const float* __restrict__ Wb) {
    size_t idx = ((size_t)blockIdx.x * 256 + threadIdx.x) * 2;
    const size_t per = (size_t)KD * KD;
    int b = (int)(idx / per);
    size_t rem = idx % per;
    int i = (int)(rem / KD), j = (int)(rem % KD);
    float s0 = 0.f, s1 = 0.f;
    for (int sp = 0; sp < M_NSPLIT; sp++) {
        const float* p = g_Mp + ((size_t)(b * M_NSPLIT + sp)) * per + rem;
        s0 += p[0];
        s1 += p[1];
    }
    float u = Wb[i];
    s0 += u * g_s[b * KD + j];
    s1 += u * g_s[b * KD + j + 1];
    __nv_bfloat162 h2, l2;
    split_f32(s0, h2.x, l2.x);
    split_f32(s1, h2.y, l2.y);
    *(__nv_bfloat162*)&g_M_hi[idx] = h2;
    *(__nv_bfloat162*)&g_M_lo[idx] = l2;
}

// ---------------------------------------------------------------------------
// log_softmax over V + permute (B,L,V)->(L,B,V)
// ---------------------------------------------------------------------------
__global__ void logsoftmax_k(float* __restrict__ out) {
    int l = blockIdx.x, b = blockIdx.y;
    const float* row = g_logits + (size_t)(b * KL + l) * KVP;
    float* orow = out + (size_t)(l * KB + b) * KV;
    __shared__ float sred[8];
    int t = threadIdx.x;
    int wid = t >> 5, lane = t & 31;
    bool act = t < (KV / 4);
    float4 v = act ? *(const float4*)&row[t * 4]
                   : make_float4(-3.4e38f, -3.4e38f, -3.4e38f, -3.4e38f);
    float m = fmaxf(fmaxf(v.x, v.y), fmaxf(v.z, v.w));
#pragma unroll
    for (int s = 16; s >= 1; s >>= 1) m = fmaxf(m, __shfl_xor_sync(0xffffffffu, m, s));
    if (lane == 0) sred[wid] = m;
    __syncthreads();
    float m8 = (lane < 8) ? sred[lane] : -3.4e38f;
#pragma unroll
    for (int s = 4; s >= 1; s >>= 1) m8 = fmaxf(m8, __shfl_xor_sync(0xffffffffu, m8, s));
    float vmax = __shfl_sync(0xffffffffu, m8, 0);

    float e = act ? (__expf(v.x - vmax) + __expf(v.y - vmax) +
                     __expf(v.z - vmax) + __expf(v.w - vmax))
                  : 0.f;
#pragma unroll
    for (int s = 16; s >= 1; s >>= 1) e += __shfl_xor_sync(0xffffffffu, e, s);
    __syncthreads();
    if (lane == 0) sred[wid] = e;
    __syncthreads();
    float e8 = (lane < 8) ? sred[lane] : 0.f;
#pragma unroll
    for (int s = 4; s >= 1; s >>= 1) e8 += __shfl_xor_sync(0xffffffffu, e8, s);
    float denom = vmax + logf(__shfl_sync(0xffffffffu, e8, 0));

    if (act) {
        float4 o;
        o.x = v.x - denom; o.y = v.y - denom;
        o.z = v.z - denom; o.w = v.w - denom;
        *(float4*)&orow[t * 4] = o;
    }
}

// ---------------------------------------------------------------------------
extern "C" void kernel_launch(void* const* d_in, const int* in_sizes, int n_in,
                              void* d_out, int out_size) {
    (void)in_sizes; (void)n_in; (void)out_size;
    const float* x  = (const float*)d_in[0];
    const float* Ww = (const float*)d_in[1];
    const float* Wb = (const float*)d_in[2];
    const float* Lw = (const float*)d_in[3];
    const float* Lb = (const float*)d_in[4];
    float* out = (float*)d_out;

    static bool attr_set = false;
    if (!attr_set) {
        cudaFuncSetAttribute(mma_gemm_k, cudaFuncAttributeMaxDynamicSharedMemorySize, DYN_SMEM);
        attr_set = true;
    }

    __nv_bfloat16 *Xb_hi, *Xb_lo, *Xt_hi, *Xt_lo, *Wwh, *Wwl, *Lwh, *Lwl;
    __nv_bfloat16 *Gh, *Gl, *Mh, *Ml, *Ph, *Pl;
    float *Lbp, *logits, *Gp, *Mp;
    cudaGetSymbolAddress((void**)&Xb_hi, g_Xb_hi);
    cudaGetSymbolAddress((void**)&Xb_lo, g_Xb_lo);
    cudaGetSymbolAddress((void**)&Xt_hi, g_Xt_hi);
    cudaGetSymbolAddress((void**)&Xt_lo, g_Xt_lo);
    cudaGetSymbolAddress((void**)&Wwh, g_Ww_hi);
    cudaGetSymbolAddress((void**)&Wwl, g_Ww_lo);
    cudaGetSymbolAddress((void**)&Lwh, g_Lw_hi);
    cudaGetSymbolAddress((void**)&Lwl, g_Lw_lo);
    cudaGetSymbolAddress((void**)&Gh, g_G_hi);
    cudaGetSymbolAddress((void**)&Gl, g_G_lo);
    cudaGetSymbolAddress((void**)&Mh, g_M_hi);
    cudaGetSymbolAddress((void**)&Ml, g_M_lo);
    cudaGetSymbolAddress((void**)&Ph, g_P_hi);
    cudaGetSymbolAddress((void**)&Pl, g_P_lo);
    cudaGetSymbolAddress((void**)&Lbp, g_Lbp);
    cudaGetSymbolAddress((void**)&logits, g_logits);
    cudaGetSymbolAddress((void**)&Gp, g_Gp);
    cudaGetSymbolAddress((void**)&Mp, g_Mp);

    prep_x_k<<<dim3(KL / 64, KD / 64, KB), 256>>>(x);
    colsum_final_k<<<(KB * KD) / 256, 256>>>();
    prep_w_k<<<(KVP * KD) / 256, 256>>>(Ww, Lw, Lb);

    // G[b] = Xt*Xt^T (symmetric): 10 upper tile-pairs, K-split x3 -> 120 CTAs
    // (single wave on 148 SMs; chunks split 22/21/21 in-kernel)
    mma_gemm_k<<<dim3(10, 1, KB * G_NSPLIT), 256, DYN_SMEM>>>(
        Xt_hi, Xt_lo, (size_t)KD * KL, Xt_hi, Xt_lo, (size_t)KD * KL,
        KL, KL / 64, G_NSPLIT, nullptr, nullptr, Gp, 0, 128, nullptr, 4);
    reduce_G_k<<<(KB * KD * KD / 2) / 256, 256>>>();

    // M[b] = Ww*G[b]^T (512x512, K=512): A=Ww (unbatched), B=G (batched);
    // K-split x2; rank-1 Wb (x) s added in reduce
    mma_gemm_k<<<dim3(4, 4, KB * M_NSPLIT), 256, DYN_SMEM>>>(
        Wwh, Wwl, 0, Gh, Gl, (size_t)KD * KD,
        KD, KD / 64, M_NSPLIT, nullptr, nullptr, Mp, (size_t)KD * KD, KD, nullptr, 3);
    reduce_M_k<<<(KB * KD * KD / 2) / 256, 256>>>(Wb);

    // P[b][v][k] = sum_n Lw[v][n] * M[b][k][n]  (A=Lw, B=M) -> bf16 split
    mma_gemm_k<<<dim3(KVP / 128, KD / 128, KB), 256, DYN_SMEM>>>(
        Lwh, Lwl, 0, Mh, Ml, (size_t)KD * KD,
        KD, KD / 64, 1, Ph, Pl, nullptr, (size_t)KVP * KD, KD, nullptr, 0);

    // logits[b] = Xb * P^T + Lb  (4096x1024, K=512)
    mma_gemm_k<<<dim3(KL / 128, KVP / 128, KB), 256, DYN_SMEM>>>(
        Xb_hi, Xb_lo, (size_t)KL * KD, Ph, Pl, (size_t)KVP * KD,
        KD, KD / 64, 1, nullptr, nullptr, logits, (size_t)KL * KVP, KVP, Lbp, 2);

    logsoftmax_k<<<dim3(KL, KB), 256>>>(out);
}